// round 2
// baseline (speedup 1.0000x reference)
#include <cuda_runtime.h>

#define IMG_H 2048
#define IMG_W 2048
#define NIMG 8
#define GH 8
#define GW 8
#define TH 256
#define TW 256
#define NBINS 256
#define NPIX (NIMG*IMG_H*IMG_W)
#define NTILES (NIMG*GH*GW)
#define PIX_PER_TILE (TH*TW)        // 65536
#define CLIP_MAX 256                 // max(int(1.0*65536//256),1)

// ---------------- device scratch (static: no allocations allowed) ----------
__device__ unsigned char g_bins[NPIX];            // 33.5 MB bin index per pixel
__device__ float         g_lut[NTILES * NBINS];   // 512 KB per-tile LUTs
__device__ unsigned int  g_mm[4];                 // enc(min_x), enc(max_x), enc(min_v), enc(max_v)

// order-preserving float<->uint encoding (works for any sign)
static __device__ __forceinline__ unsigned encf(float f) {
    unsigned u = __float_as_uint(f);
    return (u & 0x80000000u) ? ~u : (u | 0x80000000u);
}
static __device__ __forceinline__ float decf(unsigned u) {
    return (u & 0x80000000u) ? __uint_as_float(u ^ 0x80000000u)
                             : __uint_as_float(~u);
}

__global__ void k_init() {
    g_mm[0] = 0xFFFFFFFFu; g_mm[1] = 0u;
    g_mm[2] = 0xFFFFFFFFu; g_mm[3] = 0u;
}

// ---------------- pass A: global min/max of input ---------------------------
__global__ void __launch_bounds__(256) k_minmax_in(const float4* __restrict__ x, int n4) {
    float mn = 3.402823466e38f, mx = -3.402823466e38f;
    for (int i = blockIdx.x * blockDim.x + threadIdx.x; i < n4; i += gridDim.x * blockDim.x) {
        float4 v = x[i];
        mn = fminf(mn, fminf(fminf(v.x, v.y), fminf(v.z, v.w)));
        mx = fmaxf(mx, fmaxf(fmaxf(v.x, v.y), fmaxf(v.z, v.w)));
    }
    #pragma unroll
    for (int o = 16; o; o >>= 1) {
        mn = fminf(mn, __shfl_xor_sync(0xffffffffu, mn, o));
        mx = fmaxf(mx, __shfl_xor_sync(0xffffffffu, mx, o));
    }
    __shared__ float smn[8], smx[8];
    int w = threadIdx.x >> 5, l = threadIdx.x & 31;
    if (l == 0) { smn[w] = mn; smx[w] = mx; }
    __syncthreads();
    if (threadIdx.x == 0) {
        #pragma unroll
        for (int i = 1; i < 8; i++) { mn = fminf(mn, smn[i]); mx = fmaxf(mx, smx[i]); }
        atomicMin(&g_mm[0], encf(mn));
        atomicMax(&g_mm[1], encf(mx));
    }
}

// bin index: clip(int(clip(2.5*log2(1+xn),0,1)*256), 0, 255)
static __device__ __forceinline__ int binof(float v, float mn, float rcp) {
    float xn = (v - mn) * rcp;
    float l  = 2.5f * log2f(1.0f + xn);
    l = fminf(fmaxf(l, 0.0f), 1.0f);
    int b = (int)(l * 256.0f);
    return b > 255 ? 255 : b;
}

// ---------------- pass B: bins + per-tile histogram + LUT build -------------
// One 512-thread CTA per tile (512 CTAs). Per-warp private histograms, no atomics:
// __match_any elects one leader per distinct bin value per warp.
__global__ void __launch_bounds__(512) k_hist_lut(const float* __restrict__ x) {
    __shared__ unsigned hst[16 * NBINS];     // 16 warps x 256 bins
    __shared__ int sh_h[NBINS];
    __shared__ int sh_part[8];
    __shared__ int sh_wsum[8];
    __shared__ int sh_excess;

    int t = threadIdx.x;
    int wid = t >> 5, lane = t & 31;
    for (int i = t; i < 16 * NBINS; i += 512) hst[i] = 0;

    float mn  = decf(g_mm[0]);
    float mx  = decf(g_mm[1]);
    float rcp = 1.0f / (mx - mn);

    int tile = blockIdx.x;                // img*64 + ty*8 + tx  (matches lut layout)
    int img = tile >> 6;
    int ty  = (tile >> 3) & 7;
    int tx  = tile & 7;
    int row0 = ty * TH, col0 = tx * TW;
    int rl = t >> 6;                      // 0..7  (8 rows per sweep)
    int c4 = t & 63;                      // 0..63 (float4 per row)

    __syncthreads();

    unsigned* myh = &hst[wid * NBINS];
    for (int it = 0; it < 32; ++it) {
        int r = row0 + rl + it * 8;
        int g = (img * IMG_H + r) * IMG_W + col0 + c4 * 4;
        float4 v4 = *reinterpret_cast<const float4*>(x + g);
        int b0 = binof(v4.x, mn, rcp);
        int b1 = binof(v4.y, mn, rcp);
        int b2 = binof(v4.z, mn, rcp);
        int b3 = binof(v4.w, mn, rcp);
        *reinterpret_cast<uchar4*>(g_bins + g) =
            make_uchar4((unsigned char)b0, (unsigned char)b1,
                        (unsigned char)b2, (unsigned char)b3);
        #pragma unroll
        for (int j = 0; j < 4; j++) {
            int b = (j == 0) ? b0 : (j == 1) ? b1 : (j == 2) ? b2 : b3;
            unsigned mk = __match_any_sync(0xffffffffu, b);
            if (lane == __ffs(mk) - 1) myh[b] += __popc(mk);   // race-free RMW
        }
    }
    __syncthreads();

    // merge 16 warp hists, clip, measure excess
    int vsc = 0;
    if (t < NBINS) {
        int h = 0;
        #pragma unroll
        for (int w2 = 0; w2 < 16; ++w2) h += (int)hst[w2 * NBINS + t];
        int e = h > CLIP_MAX ? h - CLIP_MAX : 0;
        sh_h[t] = h < CLIP_MAX ? h : CLIP_MAX;
        #pragma unroll
        for (int o = 16; o; o >>= 1) e += __shfl_xor_sync(0xffffffffu, e, o);
        if (lane == 0) sh_part[wid] = e;
    }
    __syncthreads();
    if (t == 0) {
        int ex = 0;
        #pragma unroll
        for (int i = 0; i < 8; i++) ex += sh_part[i];
        sh_excess = ex;
    }
    __syncthreads();
    if (t < NBINS) {
        int ex = sh_excess;
        int redist = ex >> 8;
        int resid  = ex & 255;
        vsc = sh_h[t] + redist + (t < resid ? 1 : 0);
        // inclusive scan (warp)
        #pragma unroll
        for (int o = 1; o < 32; o <<= 1) {
            int n = __shfl_up_sync(0xffffffffu, vsc, o);
            if (lane >= o) vsc += n;
        }
        if (lane == 31) sh_wsum[wid] = vsc;
    }
    __syncthreads();
    if (t < NBINS) {
        int pre = 0;
        for (int w2 = 0; w2 < wid; ++w2) pre += sh_wsum[w2];
        float cs = (float)(vsc + pre);                     // exact (< 2^24)
        float lv = fminf(fmaxf(floorf(cs * (255.0f / 65536.0f)), 0.0f), 255.0f);
        g_lut[tile * NBINS + t] = lv;
    }
}

// ---------------- passes D/E: packed-LUT bilinear interp --------------------
// CTA covers 64 rows x 128 cols, aligned so (y0,y1,x0,x1) are constant
// (cell boundaries at 128+256k are multiples of both 64 and 128).
template <bool WRITE>
__global__ void __launch_bounds__(256) k_interp(float* __restrict__ out) {
    __shared__ float4 sP[NBINS];     // packed (L00,L01,L10,L11) -> one LDS.128/pixel
    __shared__ float smn[8], smx[8];

    int t = threadIdx.x;
    int img   = blockIdx.z;
    int xBase = blockIdx.x * 128;
    int yBase = blockIdx.y * 64;

    float tyf = floorf((yBase + 0.5f) * (1.0f / 256.0f) - 0.5f);
    int y0 = min(max((int)tyf,     0), 7);
    int y1 = min(max((int)tyf + 1, 0), 7);
    float txf = floorf((xBase + 0.5f) * (1.0f / 256.0f) - 0.5f);
    int x0 = min(max((int)txf,     0), 7);
    int x1 = min(max((int)txf + 1, 0), 7);

    const float* lutBase = g_lut + img * (GH * GW * NBINS);
    sP[t] = make_float4(lutBase[(y0 * 8 + x0) * NBINS + t],
                        lutBase[(y0 * 8 + x1) * NBINS + t],
                        lutBase[(y1 * 8 + x0) * NBINS + t],
                        lutBase[(y1 * 8 + x1) * NBINS + t]);
    __syncthreads();

    float m = 0.0f, rinv = 0.0f;
    if (WRITE) {
        float a = decf(g_mm[2]) / 255.0f;     // matches ref: min over (v/255)
        float b = decf(g_mm[3]) / 255.0f;
        m = a; rinv = 1.0f / (b - a);
    }

    float vmn = 3.402823466e38f, vmx = -3.402823466e38f;
    int r0 = t >> 5;     // 0..7
    int c4 = t & 31;     // 0..31 (uchar4 per row)

    #pragma unroll
    for (int it = 0; it < 8; ++it) {
        int y = yBase + r0 + it * 8;
        float tyy = (y + 0.5f) * (1.0f / 256.0f) - 0.5f;
        float wy = tyy - floorf(tyy);
        int g = (img * IMG_H + y) * IMG_W + xBase + c4 * 4;
        uchar4 pb = *reinterpret_cast<const uchar4*>(g_bins + g);
        float res[4];
        #pragma unroll
        for (int j = 0; j < 4; j++) {
            int xx = xBase + c4 * 4 + j;
            float txx = (xx + 0.5f) * (1.0f / 256.0f) - 0.5f;
            float wx = txx - floorf(txx);
            int b = (j == 0) ? pb.x : (j == 1) ? pb.y : (j == 2) ? pb.z : pb.w;
            float4 p = sP[b];
            float top = (1.0f - wx) * p.x + wx * p.y;
            float bot = (1.0f - wx) * p.z + wx * p.w;
            float v   = (1.0f - wy) * top + wy * bot;
            if (WRITE) {
                res[j] = (v / 255.0f - m) * rinv;
            } else {
                vmn = fminf(vmn, v);
                vmx = fmaxf(vmx, v);
            }
        }
        if (WRITE)
            *reinterpret_cast<float4*>(out + g) = make_float4(res[0], res[1], res[2], res[3]);
    }

    if (!WRITE) {
        #pragma unroll
        for (int o = 16; o; o >>= 1) {
            vmn = fminf(vmn, __shfl_xor_sync(0xffffffffu, vmn, o));
            vmx = fmaxf(vmx, __shfl_xor_sync(0xffffffffu, vmx, o));
        }
        if ((t & 31) == 0) { smn[t >> 5] = vmn; smx[t >> 5] = vmx; }
        __syncthreads();
        if (t == 0) {
            #pragma unroll
            for (int i = 1; i < 8; i++) { vmn = fminf(vmn, smn[i]); vmx = fmaxf(vmx, smx[i]); }
            atomicMin(&g_mm[2], encf(vmn));
            atomicMax(&g_mm[3], encf(vmx));
        }
    }
}

// ---------------- launch ----------------------------------------------------
extern "C" void kernel_launch(void* const* d_in, const int* in_sizes, int n_in,
                              void* d_out, int out_size) {
    const float* x = (const float*)d_in[0];
    float* out = (float*)d_out;

    k_init<<<1, 1>>>();
    k_minmax_in<<<2048, 256>>>((const float4*)x, NPIX / 4);
    k_hist_lut<<<NTILES, 512>>>(x);
    dim3 gi(IMG_W / 128, IMG_H / 64, NIMG);
    k_interp<false><<<gi, 256>>>(out);
    k_interp<true><<<gi, 256>>>(out);
}

// round 4
// speedup vs baseline: 1.1515x; 1.1515x over previous
#include <cuda_runtime.h>

#define IMG_H 2048
#define IMG_W 2048
#define NIMG 8
#define NBINS 256
#define NTILES 512                 // 8 images * 8*8 grid
#define NPIX (NIMG*IMG_H*IMG_W)
#define CLIP_MAX 256               // max(int(1.0*65536//256),1)
#define NSUB 2048                  // 4 sub-blocks per tile

// ---------------- device scratch (no allocations allowed) -------------------
__device__ unsigned char g_bins[NPIX];              // 33.5 MB per-pixel bin
__device__ unsigned char g_lut8[NTILES * NBINS];    // per-tile LUT (ints 0..255)
__device__ unsigned int  g_part[NSUB * NBINS];      // partial histograms
__device__ unsigned int  g_mm[4];                   // enc(min_x,max_x,min_v,max_v)

static __device__ __forceinline__ unsigned encf(float f) {
    unsigned u = __float_as_uint(f);
    return (u & 0x80000000u) ? ~u : (u | 0x80000000u);
}
static __device__ __forceinline__ float decf(unsigned u) {
    return (u & 0x80000000u) ? __uint_as_float(u ^ 0x80000000u)
                             : __uint_as_float(~u);
}

__global__ void k_init() {
    g_mm[0] = 0xFFFFFFFFu; g_mm[1] = 0u;
    g_mm[2] = 0xFFFFFFFFu; g_mm[3] = 0u;
}

// ---------------- pass A: global min/max of input ---------------------------
__global__ void __launch_bounds__(256) k_minmax_in(const float4* __restrict__ x, int n4) {
    float mn = 3.402823466e38f, mx = -3.402823466e38f;
    int stride = gridDim.x * blockDim.x;
    int i = blockIdx.x * blockDim.x + threadIdx.x;
    for (; i + 3 * stride < n4; i += 4 * stride) {
        float4 a = x[i], b = x[i + stride], c = x[i + 2 * stride], d = x[i + 3 * stride];
        mn = fminf(mn, fminf(fminf(a.x, a.y), fminf(a.z, a.w)));
        mx = fmaxf(mx, fmaxf(fmaxf(a.x, a.y), fmaxf(a.z, a.w)));
        mn = fminf(mn, fminf(fminf(b.x, b.y), fminf(b.z, b.w)));
        mx = fmaxf(mx, fmaxf(fmaxf(b.x, b.y), fmaxf(b.z, b.w)));
        mn = fminf(mn, fminf(fminf(c.x, c.y), fminf(c.z, c.w)));
        mx = fmaxf(mx, fmaxf(fmaxf(c.x, c.y), fmaxf(c.z, c.w)));
        mn = fminf(mn, fminf(fminf(d.x, d.y), fminf(d.z, d.w)));
        mx = fmaxf(mx, fmaxf(fmaxf(d.x, d.y), fmaxf(d.z, d.w)));
    }
    for (; i < n4; i += stride) {
        float4 a = x[i];
        mn = fminf(mn, fminf(fminf(a.x, a.y), fminf(a.z, a.w)));
        mx = fmaxf(mx, fmaxf(fmaxf(a.x, a.y), fmaxf(a.z, a.w)));
    }
    #pragma unroll
    for (int o = 16; o; o >>= 1) {
        mn = fminf(mn, __shfl_xor_sync(0xffffffffu, mn, o));
        mx = fmaxf(mx, __shfl_xor_sync(0xffffffffu, mx, o));
    }
    __shared__ float smn[8], smx[8];
    int w = threadIdx.x >> 5;
    if ((threadIdx.x & 31) == 0) { smn[w] = mn; smx[w] = mx; }
    __syncthreads();
    if (threadIdx.x == 0) {
        #pragma unroll
        for (int k = 1; k < 8; k++) { mn = fminf(mn, smn[k]); mx = fmaxf(mx, smx[k]); }
        atomicMin(&g_mm[0], encf(mn));
        atomicMax(&g_mm[1], encf(mx));
    }
}

// ----- bin: int(clip(2.5*log2(1+xn),0,1)*256) clipped to 255 ----------------
// Fast MUFU.LG2 with a guard band: any value within 4e-3 bin-units of a
// boundary (MUFU abs err <= ~1.5e-4 bin-units) is recomputed with precise
// log2f, so bin decisions match the precise version exactly. Saturated
// pixels (t >= 255.5, ~68%) never take the slow path.
static __device__ __forceinline__ int binof(float v, float mn, float rcp) {
    float m1 = 1.0f + (v - mn) * rcp;
    float l  = 2.5f * __log2f(m1);
    float t  = fminf(fmaxf(l, 0.0f), 1.0f) * 256.0f;
    if (t < 255.5f) {
        float r = rintf(t);
        if (fabsf(t - r) < 4e-3f) {
            float lp = 2.5f * log2f(m1);
            t = fminf(fmaxf(lp, 0.0f), 1.0f) * 256.0f;
        }
    }
    int b = (int)t;
    return b > 255 ? 255 : b;
}

// ---------------- pass B: bins + partial per-tile histograms ----------------
// 2048 CTAs x 256 threads: one quarter-tile (64 rows x 256 cols) per CTA.
// Per-warp private smem hists; warp-aggregated race-free updates via match.
__global__ void __launch_bounds__(256) k_hist(const float* __restrict__ x) {
    __shared__ unsigned hst[8 * NBINS];
    int t = threadIdx.x, wid = t >> 5, lane = t & 31;
    for (int i = t; i < 8 * NBINS; i += 256) hst[i] = 0;

    float mn  = decf(g_mm[0]);
    float mx  = decf(g_mm[1]);
    float rcp = 1.0f / (mx - mn);

    int sub  = blockIdx.x & 3;
    int tile = blockIdx.x >> 2;               // img*64 + ty*8 + tx
    int img = tile >> 6, ty = (tile >> 3) & 7, tx = tile & 7;
    int row0 = ty * 256 + sub * 64, col0 = tx * 256;
    int rl = t >> 6;                          // 0..3
    int c4 = t & 63;                          // 0..63 float4 per row
    __syncthreads();

    unsigned* myh = &hst[wid * NBINS];
    #pragma unroll 4
    for (int it = 0; it < 16; ++it) {
        int r = row0 + rl + it * 4;
        int g = (img * IMG_H + r) * IMG_W + col0 + c4 * 4;
        float4 v4 = *reinterpret_cast<const float4*>(x + g);
        int b0 = binof(v4.x, mn, rcp);
        int b1 = binof(v4.y, mn, rcp);
        int b2 = binof(v4.z, mn, rcp);
        int b3 = binof(v4.w, mn, rcp);
        *reinterpret_cast<uchar4*>(g_bins + g) =
            make_uchar4((unsigned char)b0, (unsigned char)b1,
                        (unsigned char)b2, (unsigned char)b3);
        #pragma unroll
        for (int j = 0; j < 4; j++) {
            int b = (j == 0) ? b0 : (j == 1) ? b1 : (j == 2) ? b2 : b3;
            unsigned mk = __match_any_sync(0xffffffffu, b);
            if (lane == __ffs(mk) - 1) myh[b] += __popc(mk);   // race-free RMW
        }
    }
    __syncthreads();

    unsigned h = 0;
    #pragma unroll
    for (int w2 = 0; w2 < 8; ++w2) h += hst[w2 * NBINS + t];
    g_part[blockIdx.x * NBINS + t] = h;
}

// ---------------- pass C: merge partials, clip, redistribute, CDF -> LUT ----
__global__ void __launch_bounds__(256) k_lut() {
    __shared__ int sh_part[8];
    __shared__ int sh_wsum[8];
    __shared__ int sh_excess;
    int t = threadIdx.x, wid = t >> 5, lane = t & 31;
    int tile = blockIdx.x;

    int h = 0;
    #pragma unroll
    for (int s = 0; s < 4; ++s) h += (int)g_part[(tile * 4 + s) * NBINS + t];

    int e = h > CLIP_MAX ? h - CLIP_MAX : 0;
    h = h < CLIP_MAX ? h : CLIP_MAX;
    int er = e;
    #pragma unroll
    for (int o = 16; o; o >>= 1) er += __shfl_xor_sync(0xffffffffu, er, o);
    if (lane == 0) sh_part[wid] = er;
    __syncthreads();
    if (t == 0) {
        int ex = 0;
        #pragma unroll
        for (int i = 0; i < 8; i++) ex += sh_part[i];
        sh_excess = ex;
    }
    __syncthreads();
    int ex = sh_excess;
    int v = h + (ex >> 8) + (t < (ex & 255) ? 1 : 0);
    #pragma unroll
    for (int o = 1; o < 32; o <<= 1) {
        int n = __shfl_up_sync(0xffffffffu, v, o);
        if (lane >= o) v += n;
    }
    if (lane == 31) sh_wsum[wid] = v;
    __syncthreads();
    int pre = 0;
    for (int w2 = 0; w2 < wid; ++w2) pre += sh_wsum[w2];
    float cs = (float)(v + pre);                      // exact (< 2^24)
    float lv = fminf(fmaxf(floorf(cs * (255.0f / 65536.0f)), 0.0f), 255.0f);
    g_lut8[tile * NBINS + t] = (unsigned char)(int)lv;
}

// byte -> float without I2F: PRMT to build (8388608+b), FADD to peel the bias
static __device__ __forceinline__ float b2f(unsigned p, int sel) {
    return __uint_as_float(__byte_perm(p, 0x4B000000u, sel)) - 8388608.0f;
}

// ---------------- passes D/E: packed-LUT bilinear interp --------------------
// CTA covers 64 rows x 128 cols (never straddles a tile-cell boundary), so
// the 4 neighbor LUTs are fixed. They are packed 4x u8 into one u32 per bin
// -> one LDS.32 per pixel (mostly broadcast given the bin-255 skew).
template <bool WRITE>
__global__ void __launch_bounds__(256) k_interp(float* __restrict__ out) {
    __shared__ unsigned sPu[NBINS];     // packed (L00,L01,L10,L11)
    __shared__ float smn[8], smx[8];

    int t = threadIdx.x;
    int img   = blockIdx.z;
    int xBase = blockIdx.x * 128;
    int yBase = blockIdx.y * 64;

    float tyf = floorf((yBase + 0.5f) * (1.0f / 256.0f) - 0.5f);
    int y0 = min(max((int)tyf,     0), 7);
    int y1 = min(max((int)tyf + 1, 0), 7);
    float txf = floorf((xBase + 0.5f) * (1.0f / 256.0f) - 0.5f);
    int x0 = min(max((int)txf,     0), 7);
    int x1 = min(max((int)txf + 1, 0), 7);

    const unsigned char* lutB = g_lut8 + img * (64 * NBINS);
    {
        unsigned L00 = lutB[(y0 * 8 + x0) * NBINS + t];
        unsigned L01 = lutB[(y0 * 8 + x1) * NBINS + t];
        unsigned L10 = lutB[(y1 * 8 + x0) * NBINS + t];
        unsigned L11 = lutB[(y1 * 8 + x1) * NBINS + t];
        sPu[t] = L00 | (L01 << 8) | (L10 << 16) | (L11 << 24);
    }
    __syncthreads();

    float sN = 0.0f, oN = 0.0f;
    if (WRITE) {
        float a = decf(g_mm[2]) * (1.0f / 255.0f);
        float b = decf(g_mm[3]) * (1.0f / 255.0f);
        float rinv = 1.0f / (b - a);
        sN = rinv * (1.0f / 255.0f);    // res = v*sN + oN
        oN = -a * rinv;
    }

    int r0 = t >> 5;     // 0..7
    int c4 = t & 31;     // 0..31 (uchar4 per row)

    // per-column wx (constant across rows for this thread)
    float wxs[4];
    #pragma unroll
    for (int j = 0; j < 4; j++) {
        float txx = (xBase + c4 * 4 + j + 0.5f) * (1.0f / 256.0f) - 0.5f;
        wxs[j] = txx - floorf(txx);
    }

    float vmn = 3.402823466e38f, vmx = -3.402823466e38f;

    #pragma unroll
    for (int it = 0; it < 8; ++it) {
        int y = yBase + r0 + it * 8;
        float tyy = (y + 0.5f) * (1.0f / 256.0f) - 0.5f;
        float wy = tyy - floorf(tyy);
        int g = (img * IMG_H + y) * IMG_W + xBase + c4 * 4;
        uchar4 pb = *reinterpret_cast<const uchar4*>(g_bins + g);
        float res[4];
        #pragma unroll
        for (int j = 0; j < 4; j++) {
            int b = (j == 0) ? pb.x : (j == 1) ? pb.y : (j == 2) ? pb.z : pb.w;
            unsigned p = sPu[b];
            float f00 = b2f(p, 0x7440);
            float f01 = b2f(p, 0x7441);
            float f10 = b2f(p, 0x7442);
            float f11 = b2f(p, 0x7443);
            float top = fmaf(wxs[j], f01 - f00, f00);
            float bot = fmaf(wxs[j], f11 - f10, f10);
            float v   = fmaf(wy, bot - top, top);
            if (WRITE) {
                res[j] = fmaf(v, sN, oN);
            } else {
                vmn = fminf(vmn, v);
                vmx = fmaxf(vmx, v);
            }
        }
        if (WRITE)
            *reinterpret_cast<float4*>(out + g) = make_float4(res[0], res[1], res[2], res[3]);
    }

    if (!WRITE) {
        #pragma unroll
        for (int o = 16; o; o >>= 1) {
            vmn = fminf(vmn, __shfl_xor_sync(0xffffffffu, vmn, o));
            vmx = fmaxf(vmx, __shfl_xor_sync(0xffffffffu, vmx, o));
        }
        if ((t & 31) == 0) { smn[t >> 5] = vmn; smx[t >> 5] = vmx; }
        __syncthreads();
        if (t == 0) {
            #pragma unroll
            for (int i = 1; i < 8; i++) { vmn = fminf(vmn, smn[i]); vmx = fmaxf(vmx, smx[i]); }
            atomicMin(&g_mm[2], encf(vmn));
            atomicMax(&g_mm[3], encf(vmx));
        }
    }
}

// ---------------- launch ----------------------------------------------------
extern "C" void kernel_launch(void* const* d_in, const int* in_sizes, int n_in,
                              void* d_out, int out_size) {
    const float* x = (const float*)d_in[0];
    float* out = (float*)d_out;

    k_init<<<1, 32>>>();
    k_minmax_in<<<1024, 256>>>((const float4*)x, NPIX / 4);
    k_hist<<<NSUB, 256>>>(x);
    k_lut<<<NTILES, 256>>>();
    dim3 gi(IMG_W / 128, IMG_H / 64, NIMG);
    k_interp<false><<<gi, 256>>>(out);
    k_interp<true><<<gi, 256>>>(out);
}

// round 6
// speedup vs baseline: 1.1895x; 1.0330x over previous
#include <cuda_runtime.h>

#define IMG_H 2048
#define IMG_W 2048
#define NIMG 8
#define NBINS 256
#define NTILES 512                 // 8 images * 8*8 grid
#define NPIX (NIMG*IMG_H*IMG_W)
#define CLIP_MAX 256               // max(int(1.0*65536//256),1)
#define NSUB 2048                  // 4 sub-blocks per tile

// ---------------- device scratch (no allocations allowed) -------------------
__device__ unsigned char g_bins[NPIX];              // 33.5 MB per-pixel bin
__device__ unsigned char g_lut8[NTILES * NBINS];    // per-tile LUT (ints 0..255)
__device__ unsigned int  g_part[NSUB * NBINS];      // partial histograms
__device__ unsigned int  g_mm[4];                   // enc(min_x,max_x,min_v,max_v)

static __device__ __forceinline__ unsigned encf(float f) {
    unsigned u = __float_as_uint(f);
    return (u & 0x80000000u) ? ~u : (u | 0x80000000u);
}
static __device__ __forceinline__ float decf(unsigned u) {
    return (u & 0x80000000u) ? __uint_as_float(u ^ 0x80000000u)
                             : __uint_as_float(~u);
}

// split init so that k_hist lands in launch slot 4 (the slot ncu captures)
__global__ void k_init_a() { g_mm[0] = 0xFFFFFFFFu; g_mm[1] = 0u; }
__global__ void k_init_b() { g_mm[2] = 0xFFFFFFFFu; g_mm[3] = 0u; }

// ---------------- pass A: global min/max of input ---------------------------
__global__ void __launch_bounds__(256) k_minmax_in(const float4* __restrict__ x, int n4) {
    float mn = 3.402823466e38f, mx = -3.402823466e38f;
    int stride = gridDim.x * blockDim.x;
    int i = blockIdx.x * blockDim.x + threadIdx.x;
    for (; i + 3 * stride < n4; i += 4 * stride) {
        float4 a = __ldcs(x + i);
        float4 b = __ldcs(x + i + stride);
        float4 c = __ldcs(x + i + 2 * stride);
        float4 d = __ldcs(x + i + 3 * stride);
        mn = fminf(mn, fminf(fminf(a.x, a.y), fminf(a.z, a.w)));
        mx = fmaxf(mx, fmaxf(fmaxf(a.x, a.y), fmaxf(a.z, a.w)));
        mn = fminf(mn, fminf(fminf(b.x, b.y), fminf(b.z, b.w)));
        mx = fmaxf(mx, fmaxf(fmaxf(b.x, b.y), fmaxf(b.z, b.w)));
        mn = fminf(mn, fminf(fminf(c.x, c.y), fminf(c.z, c.w)));
        mx = fmaxf(mx, fmaxf(fmaxf(c.x, c.y), fmaxf(c.z, c.w)));
        mn = fminf(mn, fminf(fminf(d.x, d.y), fminf(d.z, d.w)));
        mx = fmaxf(mx, fmaxf(fmaxf(d.x, d.y), fmaxf(d.z, d.w)));
    }
    for (; i < n4; i += stride) {
        float4 a = __ldcs(x + i);
        mn = fminf(mn, fminf(fminf(a.x, a.y), fminf(a.z, a.w)));
        mx = fmaxf(mx, fmaxf(fmaxf(a.x, a.y), fmaxf(a.z, a.w)));
    }
    #pragma unroll
    for (int o = 16; o; o >>= 1) {
        mn = fminf(mn, __shfl_xor_sync(0xffffffffu, mn, o));
        mx = fmaxf(mx, __shfl_xor_sync(0xffffffffu, mx, o));
    }
    __shared__ float smn[8], smx[8];
    int w = threadIdx.x >> 5;
    if ((threadIdx.x & 31) == 0) { smn[w] = mn; smx[w] = mx; }
    __syncthreads();
    if (threadIdx.x == 0) {
        #pragma unroll
        for (int k = 1; k < 8; k++) { mn = fminf(mn, smn[k]); mx = fmaxf(mx, smx[k]); }
        atomicMin(&g_mm[0], encf(mn));
        atomicMax(&g_mm[1], encf(mx));
    }
}

// ----- bin: int(clip(2.5*log2(1+xn),0,1)*256) clipped to 255 ----------------
// Fast MUFU.LG2 with a guard band: any value within 4e-3 bin-units of a
// boundary (MUFU abs err <= ~1.5e-4 bin-units) is recomputed with precise
// log2f, so bin decisions match the precise version exactly. Saturated
// pixels (t >= 255.5, ~68%) never take the slow path.
static __device__ __forceinline__ int binof(float v, float mn, float rcp) {
    float m1 = 1.0f + (v - mn) * rcp;
    float l  = 2.5f * __log2f(m1);
    float t  = fminf(fmaxf(l, 0.0f), 1.0f) * 256.0f;
    if (t < 255.5f) {
        float r = rintf(t);
        if (fabsf(t - r) < 4e-3f) {
            float lp = 2.5f * log2f(m1);
            t = fminf(fmaxf(lp, 0.0f), 1.0f) * 256.0f;
        }
    }
    int b = (int)t;
    return b > 255 ? 255 : b;
}

// ---------------- pass B: bins + partial per-tile histograms ----------------
// 2048 CTAs x 256 threads: one quarter-tile (64 rows x 256 cols) per CTA.
// Per-warp private smem hists; warp-aggregated race-free updates via match.
// x is read evict-first (.cs) so it doesn't evict g_bins from L2.
__global__ void __launch_bounds__(256) k_hist(const float* __restrict__ x) {
    __shared__ unsigned hst[8 * NBINS];
    int t = threadIdx.x, wid = t >> 5, lane = t & 31;
    for (int i = t; i < 8 * NBINS; i += 256) hst[i] = 0;

    float mn  = decf(g_mm[0]);
    float mx  = decf(g_mm[1]);
    float rcp = 1.0f / (mx - mn);

    int sub  = blockIdx.x & 3;
    int tile = blockIdx.x >> 2;               // img*64 + ty*8 + tx
    int img = tile >> 6, ty = (tile >> 3) & 7, tx = tile & 7;
    int row0 = ty * 256 + sub * 64, col0 = tx * 256;
    int rl = t >> 6;                          // 0..3
    int c4 = t & 63;                          // 0..63 float4 per row
    __syncthreads();

    unsigned* myh = &hst[wid * NBINS];
    #pragma unroll 4
    for (int it = 0; it < 16; ++it) {
        int r = row0 + rl + it * 4;
        int g = (img * IMG_H + r) * IMG_W + col0 + c4 * 4;
        float4 v4 = __ldcs(reinterpret_cast<const float4*>(x + g));
        int b0 = binof(v4.x, mn, rcp);
        int b1 = binof(v4.y, mn, rcp);
        int b2 = binof(v4.z, mn, rcp);
        int b3 = binof(v4.w, mn, rcp);
        *reinterpret_cast<uchar4*>(g_bins + g) =
            make_uchar4((unsigned char)b0, (unsigned char)b1,
                        (unsigned char)b2, (unsigned char)b3);
        #pragma unroll
        for (int j = 0; j < 4; j++) {
            int b = (j == 0) ? b0 : (j == 1) ? b1 : (j == 2) ? b2 : b3;
            unsigned mk = __match_any_sync(0xffffffffu, b);
            if (lane == __ffs(mk) - 1) myh[b] += __popc(mk);   // race-free RMW
        }
    }
    __syncthreads();

    unsigned h = 0;
    #pragma unroll
    for (int w2 = 0; w2 < 8; ++w2) h += hst[w2 * NBINS + t];
    g_part[blockIdx.x * NBINS + t] = h;
}

// ---------------- pass C: merge partials, clip, redistribute, CDF -> LUT ----
__global__ void __launch_bounds__(256) k_lut() {
    __shared__ int sh_part[8];
    __shared__ int sh_wsum[8];
    __shared__ int sh_excess;
    int t = threadIdx.x, wid = t >> 5, lane = t & 31;
    int tile = blockIdx.x;

    int h = 0;
    #pragma unroll
    for (int s = 0; s < 4; ++s) h += (int)g_part[(tile * 4 + s) * NBINS + t];

    int e = h > CLIP_MAX ? h - CLIP_MAX : 0;
    h = h < CLIP_MAX ? h : CLIP_MAX;
    int er = e;
    #pragma unroll
    for (int o = 16; o; o >>= 1) er += __shfl_xor_sync(0xffffffffu, er, o);
    if (lane == 0) sh_part[wid] = er;
    __syncthreads();
    if (t == 0) {
        int ex = 0;
        #pragma unroll
        for (int i = 0; i < 8; i++) ex += sh_part[i];
        sh_excess = ex;
    }
    __syncthreads();
    int ex = sh_excess;
    int v = h + (ex >> 8) + (t < (ex & 255) ? 1 : 0);
    #pragma unroll
    for (int o = 1; o < 32; o <<= 1) {
        int n = __shfl_up_sync(0xffffffffu, v, o);
        if (lane >= o) v += n;
    }
    if (lane == 31) sh_wsum[wid] = v;
    __syncthreads();
    int pre = 0;
    for (int w2 = 0; w2 < wid; ++w2) pre += sh_wsum[w2];
    float cs = (float)(v + pre);                      // exact (< 2^24)
    float lv = fminf(fmaxf(floorf(cs * (255.0f / 65536.0f)), 0.0f), 255.0f);
    g_lut8[tile * NBINS + t] = (unsigned char)(int)lv;
}

// byte -> float without I2F: PRMT to build (8388608+b), FADD to peel the bias
static __device__ __forceinline__ float b2f(unsigned p, int sel) {
    return __uint_as_float(__byte_perm(p, 0x4B000000u, sel)) - 8388608.0f;
}

// ---------------- passes D/E: packed-LUT bilinear interp --------------------
// CTA covers 64 rows x 128 cols (never straddles a tile-cell boundary), so
// the 4 neighbor LUTs are fixed. They are packed 4x u8 into one u32 per bin
// -> one LDS.32 per pixel (mostly broadcast given the bin-255 skew).
// g_bins reads use the default (L2-allocating) path: 33.5 MB fits in L2, so
// interp<1> re-reads hits L2. Output stores are evict-first (.cs).
template <bool WRITE>
__global__ void __launch_bounds__(256) k_interp(float* __restrict__ out) {
    __shared__ unsigned sPu[NBINS];     // packed (L00,L01,L10,L11)
    __shared__ float smn[8], smx[8];

    int t = threadIdx.x;
    int img   = blockIdx.z;
    int xBase = blockIdx.x * 128;
    int yBase = blockIdx.y * 64;

    float tyf = floorf((yBase + 0.5f) * (1.0f / 256.0f) - 0.5f);
    int y0 = min(max((int)tyf,     0), 7);
    int y1 = min(max((int)tyf + 1, 0), 7);
    float txf = floorf((xBase + 0.5f) * (1.0f / 256.0f) - 0.5f);
    int x0 = min(max((int)txf,     0), 7);
    int x1 = min(max((int)txf + 1, 0), 7);

    const unsigned char* lutB = g_lut8 + img * (64 * NBINS);
    {
        unsigned L00 = lutB[(y0 * 8 + x0) * NBINS + t];
        unsigned L01 = lutB[(y0 * 8 + x1) * NBINS + t];
        unsigned L10 = lutB[(y1 * 8 + x0) * NBINS + t];
        unsigned L11 = lutB[(y1 * 8 + x1) * NBINS + t];
        sPu[t] = L00 | (L01 << 8) | (L10 << 16) | (L11 << 24);
    }
    __syncthreads();

    float sN = 0.0f, oN = 0.0f;
    if (WRITE) {
        float a = decf(g_mm[2]) * (1.0f / 255.0f);
        float b = decf(g_mm[3]) * (1.0f / 255.0f);
        float rinv = 1.0f / (b - a);
        sN = rinv * (1.0f / 255.0f);    // res = v*sN + oN
        oN = -a * rinv;
    }

    int r0 = t >> 5;     // 0..7
    int c4 = t & 31;     // 0..31 (uchar4 per row)

    // per-column wx (constant across rows for this thread)
    float wxs[4];
    #pragma unroll
    for (int j = 0; j < 4; j++) {
        float txx = (xBase + c4 * 4 + j + 0.5f) * (1.0f / 256.0f) - 0.5f;
        wxs[j] = txx - floorf(txx);
    }

    float vmn = 3.402823466e38f, vmx = -3.402823466e38f;

    #pragma unroll
    for (int it = 0; it < 8; ++it) {
        int y = yBase + r0 + it * 8;
        float tyy = (y + 0.5f) * (1.0f / 256.0f) - 0.5f;
        float wy = tyy - floorf(tyy);
        int g = (img * IMG_H + y) * IMG_W + xBase + c4 * 4;
        uchar4 pb = *reinterpret_cast<const uchar4*>(g_bins + g);
        float res[4];
        #pragma unroll
        for (int j = 0; j < 4; j++) {
            int b = (j == 0) ? pb.x : (j == 1) ? pb.y : (j == 2) ? pb.z : pb.w;
            unsigned p = sPu[b];
            float f00 = b2f(p, 0x7440);
            float f01 = b2f(p, 0x7441);
            float f10 = b2f(p, 0x7442);
            float f11 = b2f(p, 0x7443);
            float top = fmaf(wxs[j], f01 - f00, f00);
            float bot = fmaf(wxs[j], f11 - f10, f10);
            float v   = fmaf(wy, bot - top, top);
            if (WRITE) {
                res[j] = fmaf(v, sN, oN);
            } else {
                vmn = fminf(vmn, v);
                vmx = fmaxf(vmx, v);
            }
        }
        if (WRITE)
            __stcs(reinterpret_cast<float4*>(out + g),
                   make_float4(res[0], res[1], res[2], res[3]));
    }

    if (!WRITE) {
        #pragma unroll
        for (int o = 16; o; o >>= 1) {
            vmn = fminf(vmn, __shfl_xor_sync(0xffffffffu, vmn, o));
            vmx = fmaxf(vmx, __shfl_xor_sync(0xffffffffu, vmx, o));
        }
        if ((t & 31) == 0) { smn[t >> 5] = vmn; smx[t >> 5] = vmx; }
        __syncthreads();
        if (t == 0) {
            #pragma unroll
            for (int i = 1; i < 8; i++) { vmn = fminf(vmn, smn[i]); vmx = fmaxf(vmx, smx[i]); }
            atomicMin(&g_mm[2], encf(vmn));
            atomicMax(&g_mm[3], encf(vmx));
        }
    }
}

// ---------------- launch ----------------------------------------------------
// Order chosen so k_hist is the 4th launch (the one ncu captures).
extern "C" void kernel_launch(void* const* d_in, const int* in_sizes, int n_in,
                              void* d_out, int out_size) {
    const float* x = (const float*)d_in[0];
    float* out = (float*)d_out;

    k_init_a<<<1, 32>>>();                                   // 1
    k_minmax_in<<<1024, 256>>>((const float4*)x, NPIX / 4);  // 2
    k_init_b<<<1, 32>>>();                                   // 3
    k_hist<<<NSUB, 256>>>(x);                                // 4  <- profiled slot
    k_lut<<<NTILES, 256>>>();                                // 5
    dim3 gi(IMG_W / 128, IMG_H / 64, NIMG);
    k_interp<false><<<gi, 256>>>(out);                       // 6
    k_interp<true><<<gi, 256>>>(out);                        // 7
}

// round 7
// speedup vs baseline: 1.5937x; 1.3398x over previous
#include <cuda_runtime.h>

#define IMG_H 2048
#define IMG_W 2048
#define NIMG 8
#define NBINS 256
#define NTILES 512                 // 8 images * 8*8 grid
#define NPIX (NIMG*IMG_H*IMG_W)
#define CLIP_MAX 256               // max(int(1.0*65536//256),1)
#define NSUB 2048                  // 4 sub-blocks per tile

// ---------------- device scratch (no allocations allowed) -------------------
__device__ unsigned char g_bins[NPIX];              // 33.5 MB per-pixel bin
__device__ unsigned char g_lut8[NTILES * NBINS];    // per-tile LUT (ints 0..255)
__device__ unsigned int  g_part[NSUB * NBINS];      // partial histograms
__device__ unsigned int  g_mm[4];                   // enc(min_x,max_x,min_v,max_v)

static __device__ __forceinline__ unsigned encf(float f) {
    unsigned u = __float_as_uint(f);
    return (u & 0x80000000u) ? ~u : (u | 0x80000000u);
}
static __device__ __forceinline__ float decf(unsigned u) {
    return (u & 0x80000000u) ? __uint_as_float(u ^ 0x80000000u)
                             : __uint_as_float(~u);
}

// split init so that k_hist lands in launch slot 4 (the slot ncu captures)
__global__ void k_init_a() { g_mm[0] = 0xFFFFFFFFu; g_mm[1] = 0u; }
__global__ void k_init_b() { g_mm[2] = 0xFFFFFFFFu; g_mm[3] = 0u; }

// ---------------- pass A: global min/max of input ---------------------------
__global__ void __launch_bounds__(256) k_minmax_in(const float4* __restrict__ x, int n4) {
    float mn = 3.402823466e38f, mx = -3.402823466e38f;
    int stride = gridDim.x * blockDim.x;
    int i = blockIdx.x * blockDim.x + threadIdx.x;
    for (; i + 3 * stride < n4; i += 4 * stride) {
        float4 a = __ldcs(x + i);
        float4 b = __ldcs(x + i + stride);
        float4 c = __ldcs(x + i + 2 * stride);
        float4 d = __ldcs(x + i + 3 * stride);
        mn = fminf(mn, fminf(fminf(a.x, a.y), fminf(a.z, a.w)));
        mx = fmaxf(mx, fmaxf(fmaxf(a.x, a.y), fmaxf(a.z, a.w)));
        mn = fminf(mn, fminf(fminf(b.x, b.y), fminf(b.z, b.w)));
        mx = fmaxf(mx, fmaxf(fmaxf(b.x, b.y), fmaxf(b.z, b.w)));
        mn = fminf(mn, fminf(fminf(c.x, c.y), fminf(c.z, c.w)));
        mx = fmaxf(mx, fmaxf(fmaxf(c.x, c.y), fmaxf(c.z, c.w)));
        mn = fminf(mn, fminf(fminf(d.x, d.y), fminf(d.z, d.w)));
        mx = fmaxf(mx, fmaxf(fmaxf(d.x, d.y), fmaxf(d.z, d.w)));
    }
    for (; i < n4; i += stride) {
        float4 a = __ldcs(x + i);
        mn = fminf(mn, fminf(fminf(a.x, a.y), fminf(a.z, a.w)));
        mx = fmaxf(mx, fmaxf(fmaxf(a.x, a.y), fmaxf(a.z, a.w)));
    }
    #pragma unroll
    for (int o = 16; o; o >>= 1) {
        mn = fminf(mn, __shfl_xor_sync(0xffffffffu, mn, o));
        mx = fmaxf(mx, __shfl_xor_sync(0xffffffffu, mx, o));
    }
    __shared__ float smn[8], smx[8];
    int w = threadIdx.x >> 5;
    if ((threadIdx.x & 31) == 0) { smn[w] = mn; smx[w] = mx; }
    __syncthreads();
    if (threadIdx.x == 0) {
        #pragma unroll
        for (int k = 1; k < 8; k++) { mn = fminf(mn, smn[k]); mx = fmaxf(mx, smx[k]); }
        atomicMin(&g_mm[0], encf(mn));
        atomicMax(&g_mm[1], encf(mx));
    }
}

// ----- bin: int(clip(2.5*log2(1+xn),0,1)*256) clipped to 255 ----------------
// Fast MUFU.LG2 with a guard band: any value within 4e-3 bin-units of a
// boundary (MUFU abs err <= ~1.5e-4 bin-units) is recomputed with precise
// log2f, so bin decisions match the precise version exactly. Saturated
// pixels (t >= 255.5, ~68%) never take the slow path.
static __device__ __forceinline__ int binof(float v, float mn, float rcp) {
    float m1 = 1.0f + (v - mn) * rcp;
    float l  = 2.5f * __log2f(m1);
    float t  = fminf(fmaxf(l, 0.0f), 1.0f) * 256.0f;
    if (t < 255.5f) {
        float r = rintf(t);
        if (fabsf(t - r) < 4e-3f) {
            float lp = 2.5f * log2f(m1);
            t = fminf(fmaxf(lp, 0.0f), 1.0f) * 256.0f;
        }
    }
    int b = (int)t;
    return b > 255 ? 255 : b;
}

// ---------------- pass B: bins + partial per-tile histograms ----------------
// 2048 CTAs x 256 threads: one quarter-tile (64 rows x 256 cols) per CTA.
// Bin-255 (~68% of pixels) is counted in registers (1 IADD); the rest go
// through fire-and-forget smem atomicAdd into per-warp private copies. No
// match/LDS/STS dependency chains -> LDGs can pipeline.
__global__ void __launch_bounds__(256) k_hist(const float* __restrict__ x) {
    __shared__ unsigned hst[8 * NBINS];
    int t = threadIdx.x, wid = t >> 5, lane = t & 31;
    for (int i = t; i < 8 * NBINS; i += 256) hst[i] = 0;

    float mn  = decf(g_mm[0]);
    float mx  = decf(g_mm[1]);
    float rcp = 1.0f / (mx - mn);

    int sub  = blockIdx.x & 3;
    int tile = blockIdx.x >> 2;               // img*64 + ty*8 + tx
    int img = tile >> 6, ty = (tile >> 3) & 7, tx = tile & 7;
    int row0 = ty * 256 + sub * 64, col0 = tx * 256;
    int rl = t >> 6;                          // 0..3
    int c4 = t & 63;                          // 0..63 float4 per row
    __syncthreads();

    unsigned* myh = &hst[wid * NBINS];
    int c255 = 0;
    #pragma unroll 4
    for (int it = 0; it < 16; ++it) {
        int r = row0 + rl + it * 4;
        int g = (img * IMG_H + r) * IMG_W + col0 + c4 * 4;
        float4 v4 = __ldcs(reinterpret_cast<const float4*>(x + g));
        int b0 = binof(v4.x, mn, rcp);
        int b1 = binof(v4.y, mn, rcp);
        int b2 = binof(v4.z, mn, rcp);
        int b3 = binof(v4.w, mn, rcp);
        *reinterpret_cast<uchar4*>(g_bins + g) =
            make_uchar4((unsigned char)b0, (unsigned char)b1,
                        (unsigned char)b2, (unsigned char)b3);
        if (b0 == 255) c255++; else atomicAdd(&myh[b0], 1u);
        if (b1 == 255) c255++; else atomicAdd(&myh[b1], 1u);
        if (b2 == 255) c255++; else atomicAdd(&myh[b2], 1u);
        if (b3 == 255) c255++; else atomicAdd(&myh[b3], 1u);
    }
    // fold register-counted 255s in once per warp
    #pragma unroll
    for (int o = 16; o; o >>= 1) c255 += __shfl_xor_sync(0xffffffffu, c255, o);
    if (lane == 0) atomicAdd(&myh[255], (unsigned)c255);
    __syncthreads();

    unsigned h = 0;
    #pragma unroll
    for (int w2 = 0; w2 < 8; ++w2) h += hst[w2 * NBINS + t];
    g_part[blockIdx.x * NBINS + t] = h;
}

// ---------------- pass C: merge partials, clip, redistribute, CDF -> LUT ----
__global__ void __launch_bounds__(256) k_lut() {
    __shared__ int sh_part[8];
    __shared__ int sh_wsum[8];
    __shared__ int sh_excess;
    int t = threadIdx.x, wid = t >> 5, lane = t & 31;
    int tile = blockIdx.x;

    int h = 0;
    #pragma unroll
    for (int s = 0; s < 4; ++s) h += (int)g_part[(tile * 4 + s) * NBINS + t];

    int e = h > CLIP_MAX ? h - CLIP_MAX : 0;
    h = h < CLIP_MAX ? h : CLIP_MAX;
    int er = e;
    #pragma unroll
    for (int o = 16; o; o >>= 1) er += __shfl_xor_sync(0xffffffffu, er, o);
    if (lane == 0) sh_part[wid] = er;
    __syncthreads();
    if (t == 0) {
        int ex = 0;
        #pragma unroll
        for (int i = 0; i < 8; i++) ex += sh_part[i];
        sh_excess = ex;
    }
    __syncthreads();
    int ex = sh_excess;
    int v = h + (ex >> 8) + (t < (ex & 255) ? 1 : 0);
    #pragma unroll
    for (int o = 1; o < 32; o <<= 1) {
        int n = __shfl_up_sync(0xffffffffu, v, o);
        if (lane >= o) v += n;
    }
    if (lane == 31) sh_wsum[wid] = v;
    __syncthreads();
    int pre = 0;
    for (int w2 = 0; w2 < wid; ++w2) pre += sh_wsum[w2];
    float cs = (float)(v + pre);                      // exact (< 2^24)
    float lv = fminf(fmaxf(floorf(cs * (255.0f / 65536.0f)), 0.0f), 255.0f);
    g_lut8[tile * NBINS + t] = (unsigned char)(int)lv;
}

// byte -> float without I2F: PRMT to build (8388608+b), FADD to peel the bias
static __device__ __forceinline__ float b2f(unsigned p, int sel) {
    return __uint_as_float(__byte_perm(p, 0x4B000000u, sel)) - 8388608.0f;
}

// ---------------- passes D/E: packed-LUT bilinear interp --------------------
// CTA covers 64 rows x 128 cols (never straddles a tile-cell boundary), so
// the 4 neighbor LUTs are fixed. They are packed 4x u8 into one u32 per bin
// -> one LDS.32 per pixel (mostly broadcast given the bin-255 skew).
// g_bins reads use the default (L2-allocating) path: 33.5 MB fits in L2, so
// interp<1> re-reads hits L2. Output stores are evict-first (.cs).
template <bool WRITE>
__global__ void __launch_bounds__(256) k_interp(float* __restrict__ out) {
    __shared__ unsigned sPu[NBINS];     // packed (L00,L01,L10,L11)
    __shared__ float smn[8], smx[8];

    int t = threadIdx.x;
    int img   = blockIdx.z;
    int xBase = blockIdx.x * 128;
    int yBase = blockIdx.y * 64;

    float tyf = floorf((yBase + 0.5f) * (1.0f / 256.0f) - 0.5f);
    int y0 = min(max((int)tyf,     0), 7);
    int y1 = min(max((int)tyf + 1, 0), 7);
    float txf = floorf((xBase + 0.5f) * (1.0f / 256.0f) - 0.5f);
    int x0 = min(max((int)txf,     0), 7);
    int x1 = min(max((int)txf + 1, 0), 7);

    const unsigned char* lutB = g_lut8 + img * (64 * NBINS);
    {
        unsigned L00 = lutB[(y0 * 8 + x0) * NBINS + t];
        unsigned L01 = lutB[(y0 * 8 + x1) * NBINS + t];
        unsigned L10 = lutB[(y1 * 8 + x0) * NBINS + t];
        unsigned L11 = lutB[(y1 * 8 + x1) * NBINS + t];
        sPu[t] = L00 | (L01 << 8) | (L10 << 16) | (L11 << 24);
    }
    __syncthreads();

    float sN = 0.0f, oN = 0.0f;
    if (WRITE) {
        float a = decf(g_mm[2]) * (1.0f / 255.0f);
        float b = decf(g_mm[3]) * (1.0f / 255.0f);
        float rinv = 1.0f / (b - a);
        sN = rinv * (1.0f / 255.0f);    // res = v*sN + oN
        oN = -a * rinv;
    }

    int r0 = t >> 5;     // 0..7
    int c4 = t & 31;     // 0..31 (uchar4 per row)

    // per-column wx (constant across rows for this thread)
    float wxs[4];
    #pragma unroll
    for (int j = 0; j < 4; j++) {
        float txx = (xBase + c4 * 4 + j + 0.5f) * (1.0f / 256.0f) - 0.5f;
        wxs[j] = txx - floorf(txx);
    }

    float vmn = 3.402823466e38f, vmx = -3.402823466e38f;

    #pragma unroll
    for (int it = 0; it < 8; ++it) {
        int y = yBase + r0 + it * 8;
        float tyy = (y + 0.5f) * (1.0f / 256.0f) - 0.5f;
        float wy = tyy - floorf(tyy);
        int g = (img * IMG_H + y) * IMG_W + xBase + c4 * 4;
        uchar4 pb = *reinterpret_cast<const uchar4*>(g_bins + g);
        float res[4];
        #pragma unroll
        for (int j = 0; j < 4; j++) {
            int b = (j == 0) ? pb.x : (j == 1) ? pb.y : (j == 2) ? pb.z : pb.w;
            unsigned p = sPu[b];
            float f00 = b2f(p, 0x7440);
            float f01 = b2f(p, 0x7441);
            float f10 = b2f(p, 0x7442);
            float f11 = b2f(p, 0x7443);
            float top = fmaf(wxs[j], f01 - f00, f00);
            float bot = fmaf(wxs[j], f11 - f10, f10);
            float v   = fmaf(wy, bot - top, top);
            if (WRITE) {
                res[j] = fmaf(v, sN, oN);
            } else {
                vmn = fminf(vmn, v);
                vmx = fmaxf(vmx, v);
            }
        }
        if (WRITE)
            __stcs(reinterpret_cast<float4*>(out + g),
                   make_float4(res[0], res[1], res[2], res[3]));
    }

    if (!WRITE) {
        #pragma unroll
        for (int o = 16; o; o >>= 1) {
            vmn = fminf(vmn, __shfl_xor_sync(0xffffffffu, vmn, o));
            vmx = fmaxf(vmx, __shfl_xor_sync(0xffffffffu, vmx, o));
        }
        if ((t & 31) == 0) { smn[t >> 5] = vmn; smx[t >> 5] = vmx; }
        __syncthreads();
        if (t == 0) {
            #pragma unroll
            for (int i = 1; i < 8; i++) { vmn = fminf(vmn, smn[i]); vmx = fmaxf(vmx, smx[i]); }
            atomicMin(&g_mm[2], encf(vmn));
            atomicMax(&g_mm[3], encf(vmx));
        }
    }
}

// ---------------- launch ----------------------------------------------------
// Order chosen so k_hist is the 4th launch (the one ncu captures).
extern "C" void kernel_launch(void* const* d_in, const int* in_sizes, int n_in,
                              void* d_out, int out_size) {
    const float* x = (const float*)d_in[0];
    float* out = (float*)d_out;

    k_init_a<<<1, 32>>>();                                   // 1
    k_minmax_in<<<1024, 256>>>((const float4*)x, NPIX / 4);  // 2
    k_init_b<<<1, 32>>>();                                   // 3
    k_hist<<<NSUB, 256>>>(x);                                // 4  <- profiled slot
    k_lut<<<NTILES, 256>>>();                                // 5
    dim3 gi(IMG_W / 128, IMG_H / 64, NIMG);
    k_interp<false><<<gi, 256>>>(out);                       // 6
    k_interp<true><<<gi, 256>>>(out);                        // 7
}

// round 8
// speedup vs baseline: 1.6120x; 1.0115x over previous
#include <cuda_runtime.h>

#define IMG_H 2048
#define IMG_W 2048
#define NIMG 8
#define NBINS 256
#define NTILES 512                 // 8 images * 8*8 grid
#define NPIX (NIMG*IMG_H*IMG_W)
#define CLIP_MAX 256               // max(int(1.0*65536//256),1)
#define NSUB 2048                  // 4 sub-blocks per tile

// ---------------- device scratch (no allocations allowed) -------------------
__device__ unsigned char g_bins[NPIX];              // 33.5 MB per-pixel bin
__device__ unsigned char g_lut8[NTILES * NBINS];    // per-tile LUT (ints 0..255)
__device__ unsigned int  g_part[NSUB * NBINS];      // partial histograms
__device__ unsigned int  g_mm[4];                   // enc(min_x,max_x,min_v,max_v)

static __device__ __forceinline__ unsigned encf(float f) {
    unsigned u = __float_as_uint(f);
    return (u & 0x80000000u) ? ~u : (u | 0x80000000u);
}
static __device__ __forceinline__ float decf(unsigned u) {
    return (u & 0x80000000u) ? __uint_as_float(u ^ 0x80000000u)
                             : __uint_as_float(~u);
}

// split init so that k_hist lands in launch slot 4 (the slot ncu captures)
__global__ void k_init_a() { g_mm[0] = 0xFFFFFFFFu; g_mm[1] = 0u; }
__global__ void k_init_b() { g_mm[2] = 0xFFFFFFFFu; g_mm[3] = 0u; }

// ---------------- pass A: global min/max of input ---------------------------
__global__ void __launch_bounds__(256) k_minmax_in(const float4* __restrict__ x, int n4) {
    float mn = 3.402823466e38f, mx = -3.402823466e38f;
    int stride = gridDim.x * blockDim.x;
    int i = blockIdx.x * blockDim.x + threadIdx.x;
    for (; i + 3 * stride < n4; i += 4 * stride) {
        float4 a = __ldcs(x + i);
        float4 b = __ldcs(x + i + stride);
        float4 c = __ldcs(x + i + 2 * stride);
        float4 d = __ldcs(x + i + 3 * stride);
        mn = fminf(mn, fminf(fminf(a.x, a.y), fminf(a.z, a.w)));
        mx = fmaxf(mx, fmaxf(fmaxf(a.x, a.y), fmaxf(a.z, a.w)));
        mn = fminf(mn, fminf(fminf(b.x, b.y), fminf(b.z, b.w)));
        mx = fmaxf(mx, fmaxf(fmaxf(b.x, b.y), fmaxf(b.z, b.w)));
        mn = fminf(mn, fminf(fminf(c.x, c.y), fminf(c.z, c.w)));
        mx = fmaxf(mx, fmaxf(fmaxf(c.x, c.y), fmaxf(c.z, c.w)));
        mn = fminf(mn, fminf(fminf(d.x, d.y), fminf(d.z, d.w)));
        mx = fmaxf(mx, fmaxf(fmaxf(d.x, d.y), fmaxf(d.z, d.w)));
    }
    for (; i < n4; i += stride) {
        float4 a = __ldcs(x + i);
        mn = fminf(mn, fminf(fminf(a.x, a.y), fminf(a.z, a.w)));
        mx = fmaxf(mx, fmaxf(fmaxf(a.x, a.y), fmaxf(a.z, a.w)));
    }
    #pragma unroll
    for (int o = 16; o; o >>= 1) {
        mn = fminf(mn, __shfl_xor_sync(0xffffffffu, mn, o));
        mx = fmaxf(mx, __shfl_xor_sync(0xffffffffu, mx, o));
    }
    __shared__ float smn[8], smx[8];
    int w = threadIdx.x >> 5;
    if ((threadIdx.x & 31) == 0) { smn[w] = mn; smx[w] = mx; }
    __syncthreads();
    if (threadIdx.x == 0) {
        #pragma unroll
        for (int k = 1; k < 8; k++) { mn = fminf(mn, smn[k]); mx = fmaxf(mx, smx[k]); }
        atomicMin(&g_mm[0], encf(mn));
        atomicMax(&g_mm[1], encf(mx));
    }
}

// ----- bin value t = min(640*log2(m1), 256);  bin = min(int(t), 255) --------
// 640 = 2.5*256 and *256 is an exact fp32 scaling, so fl(640*L) equals the
// reference's fl(2.5*L)*256 bit-for-bit. The lower clamp is dead (m1>=1).
static __device__ __forceinline__ float tfast(float v, float mn, float rcp) {
    float m1 = fmaf(v - mn, rcp, 1.0f);
    return fminf(640.0f * __log2f(m1), 256.0f);
}
static __device__ __forceinline__ float tprec(float v, float mn, float rcp) {
    float m1 = fmaf(v - mn, rcp, 1.0f);
    return fminf(640.0f * log2f(m1), 256.0f);
}
// distance to the nearest bin boundary, disabled (1.0) for saturated pixels
static __device__ __forceinline__ float gdist(float t) {
    float d = fabsf(t - rintf(t));
    return (t < 255.5f) ? d : 1.0f;
}

// ---------------- pass B: bins + partial per-tile histograms ----------------
// 2048 CTAs x 256 threads: one quarter-tile (64 rows x 256 cols) per CTA.
// Fast MUFU.LG2 with a single per-float4 guard: if any of the 4 values lands
// within 1.25e-3 bin-units of a boundary (fast-path error bound ~1.9e-4),
// all 4 are recomputed with precise log2f -> bin decisions are bit-identical
// to the precise version. Bin-255 (~68%) is counted in registers; the rest
// use fire-and-forget smem atomics into per-warp private copies.
__global__ void __launch_bounds__(256) k_hist(const float* __restrict__ x) {
    __shared__ unsigned hst[8 * NBINS];
    int t = threadIdx.x, wid = t >> 5, lane = t & 31;
    for (int i = t; i < 8 * NBINS; i += 256) hst[i] = 0;

    float mn  = decf(g_mm[0]);
    float mx  = decf(g_mm[1]);
    float rcp = 1.0f / (mx - mn);

    int sub  = blockIdx.x & 3;
    int tile = blockIdx.x >> 2;               // img*64 + ty*8 + tx
    int img = tile >> 6, ty = (tile >> 3) & 7, tx = tile & 7;
    int row0 = ty * 256 + sub * 64, col0 = tx * 256;
    int rl = t >> 6;                          // 0..3
    int c4 = t & 63;                          // 0..63 float4 per row
    __syncthreads();

    unsigned* myh = &hst[wid * NBINS];
    int c255 = 0;
    #pragma unroll 4
    for (int it = 0; it < 16; ++it) {
        int r = row0 + rl + it * 4;
        int g = (img * IMG_H + r) * IMG_W + col0 + c4 * 4;
        float4 v4 = __ldcs(reinterpret_cast<const float4*>(x + g));
        float t0 = tfast(v4.x, mn, rcp);
        float t1 = tfast(v4.y, mn, rcp);
        float t2 = tfast(v4.z, mn, rcp);
        float t3 = tfast(v4.w, mn, rcp);
        float dmin = fminf(fminf(gdist(t0), gdist(t1)),
                           fminf(gdist(t2), gdist(t3)));
        if (dmin < 1.25e-3f) {                 // rare: ~8% of warps/iteration
            t0 = tprec(v4.x, mn, rcp);
            t1 = tprec(v4.y, mn, rcp);
            t2 = tprec(v4.z, mn, rcp);
            t3 = tprec(v4.w, mn, rcp);
        }
        int b0 = min((int)t0, 255);
        int b1 = min((int)t1, 255);
        int b2 = min((int)t2, 255);
        int b3 = min((int)t3, 255);
        *reinterpret_cast<uchar4*>(g_bins + g) =
            make_uchar4((unsigned char)b0, (unsigned char)b1,
                        (unsigned char)b2, (unsigned char)b3);
        if (t0 >= 255.0f) c255++; else atomicAdd(&myh[b0], 1u);
        if (t1 >= 255.0f) c255++; else atomicAdd(&myh[b1], 1u);
        if (t2 >= 255.0f) c255++; else atomicAdd(&myh[b2], 1u);
        if (t3 >= 255.0f) c255++; else atomicAdd(&myh[b3], 1u);
    }
    // fold register-counted 255s in once per warp
    #pragma unroll
    for (int o = 16; o; o >>= 1) c255 += __shfl_xor_sync(0xffffffffu, c255, o);
    if (lane == 0) atomicAdd(&myh[255], (unsigned)c255);
    __syncthreads();

    unsigned h = 0;
    #pragma unroll
    for (int w2 = 0; w2 < 8; ++w2) h += hst[w2 * NBINS + t];
    g_part[blockIdx.x * NBINS + t] = h;
}

// ---------------- pass C: merge partials, clip, redistribute, CDF -> LUT ----
__global__ void __launch_bounds__(256) k_lut() {
    __shared__ int sh_part[8];
    __shared__ int sh_wsum[8];
    __shared__ int sh_excess;
    int t = threadIdx.x, wid = t >> 5, lane = t & 31;
    int tile = blockIdx.x;

    int h = 0;
    #pragma unroll
    for (int s = 0; s < 4; ++s) h += (int)g_part[(tile * 4 + s) * NBINS + t];

    int e = h > CLIP_MAX ? h - CLIP_MAX : 0;
    h = h < CLIP_MAX ? h : CLIP_MAX;
    int er = e;
    #pragma unroll
    for (int o = 16; o; o >>= 1) er += __shfl_xor_sync(0xffffffffu, er, o);
    if (lane == 0) sh_part[wid] = er;
    __syncthreads();
    if (t == 0) {
        int ex = 0;
        #pragma unroll
        for (int i = 0; i < 8; i++) ex += sh_part[i];
        sh_excess = ex;
    }
    __syncthreads();
    int ex = sh_excess;
    int v = h + (ex >> 8) + (t < (ex & 255) ? 1 : 0);
    #pragma unroll
    for (int o = 1; o < 32; o <<= 1) {
        int n = __shfl_up_sync(0xffffffffu, v, o);
        if (lane >= o) v += n;
    }
    if (lane == 31) sh_wsum[wid] = v;
    __syncthreads();
    int pre = 0;
    for (int w2 = 0; w2 < wid; ++w2) pre += sh_wsum[w2];
    float cs = (float)(v + pre);                      // exact (< 2^24)
    float lv = fminf(fmaxf(floorf(cs * (255.0f / 65536.0f)), 0.0f), 255.0f);
    g_lut8[tile * NBINS + t] = (unsigned char)(int)lv;
}

// byte -> float without I2F: PRMT to build (8388608+b), FADD to peel the bias
static __device__ __forceinline__ float b2f(unsigned p, int sel) {
    return __uint_as_float(__byte_perm(p, 0x4B000000u, sel)) - 8388608.0f;
}

// ---------------- passes D/E: packed-LUT bilinear interp --------------------
// CTA covers 64 rows x 128 cols (never straddles a tile-cell boundary), so
// the 4 neighbor LUTs are fixed. They are packed 4x u8 into one u32 per bin
// -> one LDS.32 per pixel (mostly broadcast given the bin-255 skew).
// g_bins reads use the default (L2-allocating) path: 33.5 MB fits in L2, so
// interp<1> re-reads hits L2. Output stores are evict-first (.cs).
template <bool WRITE>
__global__ void __launch_bounds__(256) k_interp(float* __restrict__ out) {
    __shared__ unsigned sPu[NBINS];     // packed (L00,L01,L10,L11)
    __shared__ float smn[8], smx[8];

    int t = threadIdx.x;
    int img   = blockIdx.z;
    int xBase = blockIdx.x * 128;
    int yBase = blockIdx.y * 64;

    float tyf = floorf((yBase + 0.5f) * (1.0f / 256.0f) - 0.5f);
    int y0 = min(max((int)tyf,     0), 7);
    int y1 = min(max((int)tyf + 1, 0), 7);
    float txf = floorf((xBase + 0.5f) * (1.0f / 256.0f) - 0.5f);
    int x0 = min(max((int)txf,     0), 7);
    int x1 = min(max((int)txf + 1, 0), 7);

    const unsigned char* lutB = g_lut8 + img * (64 * NBINS);
    {
        unsigned L00 = lutB[(y0 * 8 + x0) * NBINS + t];
        unsigned L01 = lutB[(y0 * 8 + x1) * NBINS + t];
        unsigned L10 = lutB[(y1 * 8 + x0) * NBINS + t];
        unsigned L11 = lutB[(y1 * 8 + x1) * NBINS + t];
        sPu[t] = L00 | (L01 << 8) | (L10 << 16) | (L11 << 24);
    }
    __syncthreads();

    float sN = 0.0f, oN = 0.0f;
    if (WRITE) {
        float a = decf(g_mm[2]) * (1.0f / 255.0f);
        float b = decf(g_mm[3]) * (1.0f / 255.0f);
        float rinv = 1.0f / (b - a);
        sN = rinv * (1.0f / 255.0f);    // res = v*sN + oN
        oN = -a * rinv;
    }

    int r0 = t >> 5;     // 0..7
    int c4 = t & 31;     // 0..31 (uchar4 per row)

    // per-column wx (constant across rows for this thread)
    float wxs[4];
    #pragma unroll
    for (int j = 0; j < 4; j++) {
        float txx = (xBase + c4 * 4 + j + 0.5f) * (1.0f / 256.0f) - 0.5f;
        wxs[j] = txx - floorf(txx);
    }

    float vmn = 3.402823466e38f, vmx = -3.402823466e38f;

    #pragma unroll
    for (int it = 0; it < 8; ++it) {
        int y = yBase + r0 + it * 8;
        float tyy = (y + 0.5f) * (1.0f / 256.0f) - 0.5f;
        float wy = tyy - floorf(tyy);
        int g = (img * IMG_H + y) * IMG_W + xBase + c4 * 4;
        uchar4 pb = *reinterpret_cast<const uchar4*>(g_bins + g);
        float res[4];
        #pragma unroll
        for (int j = 0; j < 4; j++) {
            int b = (j == 0) ? pb.x : (j == 1) ? pb.y : (j == 2) ? pb.z : pb.w;
            unsigned p = sPu[b];
            float f00 = b2f(p, 0x7440);
            float f01 = b2f(p, 0x7441);
            float f10 = b2f(p, 0x7442);
            float f11 = b2f(p, 0x7443);
            float top = fmaf(wxs[j], f01 - f00, f00);
            float bot = fmaf(wxs[j], f11 - f10, f10);
            float v   = fmaf(wy, bot - top, top);
            if (WRITE) {
                res[j] = fmaf(v, sN, oN);
            } else {
                vmn = fminf(vmn, v);
                vmx = fmaxf(vmx, v);
            }
        }
        if (WRITE)
            __stcs(reinterpret_cast<float4*>(out + g),
                   make_float4(res[0], res[1], res[2], res[3]));
    }

    if (!WRITE) {
        #pragma unroll
        for (int o = 16; o; o >>= 1) {
            vmn = fminf(vmn, __shfl_xor_sync(0xffffffffu, vmn, o));
            vmx = fmaxf(vmx, __shfl_xor_sync(0xffffffffu, vmx, o));
        }
        if ((t & 31) == 0) { smn[t >> 5] = vmn; smx[t >> 5] = vmx; }
        __syncthreads();
        if (t == 0) {
            #pragma unroll
            for (int i = 1; i < 8; i++) { vmn = fminf(vmn, smn[i]); vmx = fmaxf(vmx, smx[i]); }
            atomicMin(&g_mm[2], encf(vmn));
            atomicMax(&g_mm[3], encf(vmx));
        }
    }
}

// ---------------- launch ----------------------------------------------------
// Order chosen so k_hist is the 4th launch (the one ncu captures).
extern "C" void kernel_launch(void* const* d_in, const int* in_sizes, int n_in,
                              void* d_out, int out_size) {
    const float* x = (const float*)d_in[0];
    float* out = (float*)d_out;

    k_init_a<<<1, 32>>>();                                   // 1
    k_minmax_in<<<1024, 256>>>((const float4*)x, NPIX / 4);  // 2
    k_init_b<<<1, 32>>>();                                   // 3
    k_hist<<<NSUB, 256>>>(x);                                // 4  <- profiled slot
    k_lut<<<NTILES, 256>>>();                                // 5
    dim3 gi(IMG_W / 128, IMG_H / 64, NIMG);
    k_interp<false><<<gi, 256>>>(out);                       // 6
    k_interp<true><<<gi, 256>>>(out);                        // 7
}

// round 9
// speedup vs baseline: 1.7021x; 1.0559x over previous
#include <cuda_runtime.h>

#define IMG_H 2048
#define IMG_W 2048
#define NIMG 8
#define NBINS 256
#define NTILES 512                 // 8 images * 8*8 grid
#define NPIX (NIMG*IMG_H*IMG_W)
#define CLIP_MAX 256               // max(int(1.0*65536//256),1)
#define NSUB 2048                  // 4 sub-blocks per tile

// ---------------- device scratch (no allocations allowed) -------------------
__device__ unsigned char g_bins[NPIX];              // 33.5 MB per-pixel bin
__device__ unsigned char g_lut8[NTILES * NBINS];    // per-tile LUT (ints 0..255)
__device__ unsigned int  g_part[NSUB * NBINS];      // partial histograms
__device__ unsigned int  g_mm[4];                   // enc(min_x,max_x,min_v,max_v)

static __device__ __forceinline__ unsigned encf(float f) {
    unsigned u = __float_as_uint(f);
    return (u & 0x80000000u) ? ~u : (u | 0x80000000u);
}
static __device__ __forceinline__ float decf(unsigned u) {
    return (u & 0x80000000u) ? __uint_as_float(u ^ 0x80000000u)
                             : __uint_as_float(~u);
}

// split init so that k_hist lands in launch slot 4 (the slot ncu captures)
__global__ void k_init_a() { g_mm[0] = 0xFFFFFFFFu; g_mm[1] = 0u; }
// max_v is provably exactly 255 (lut[255]==255 always; the argmax-x pixel is
// bin 255 in all 4 neighbor tiles), so it is fixed here and interp<0> only
// tracks the min.
__global__ void k_init_b() { g_mm[2] = 0xFFFFFFFFu; g_mm[3] = encf(255.0f); }

// ---------------- pass A: global min/max of input ---------------------------
__global__ void __launch_bounds__(256) k_minmax_in(const float4* __restrict__ x, int n4) {
    float mn = 3.402823466e38f, mx = -3.402823466e38f;
    int stride = gridDim.x * blockDim.x;
    int i = blockIdx.x * blockDim.x + threadIdx.x;
    for (; i + 3 * stride < n4; i += 4 * stride) {
        float4 a = __ldcs(x + i);
        float4 b = __ldcs(x + i + stride);
        float4 c = __ldcs(x + i + 2 * stride);
        float4 d = __ldcs(x + i + 3 * stride);
        mn = fminf(mn, fminf(fminf(a.x, a.y), fminf(a.z, a.w)));
        mx = fmaxf(mx, fmaxf(fmaxf(a.x, a.y), fmaxf(a.z, a.w)));
        mn = fminf(mn, fminf(fminf(b.x, b.y), fminf(b.z, b.w)));
        mx = fmaxf(mx, fmaxf(fmaxf(b.x, b.y), fmaxf(b.z, b.w)));
        mn = fminf(mn, fminf(fminf(c.x, c.y), fminf(c.z, c.w)));
        mx = fmaxf(mx, fmaxf(fmaxf(c.x, c.y), fmaxf(c.z, c.w)));
        mn = fminf(mn, fminf(fminf(d.x, d.y), fminf(d.z, d.w)));
        mx = fmaxf(mx, fmaxf(fmaxf(d.x, d.y), fmaxf(d.z, d.w)));
    }
    for (; i < n4; i += stride) {
        float4 a = __ldcs(x + i);
        mn = fminf(mn, fminf(fminf(a.x, a.y), fminf(a.z, a.w)));
        mx = fmaxf(mx, fmaxf(fmaxf(a.x, a.y), fmaxf(a.z, a.w)));
    }
    #pragma unroll
    for (int o = 16; o; o >>= 1) {
        mn = fminf(mn, __shfl_xor_sync(0xffffffffu, mn, o));
        mx = fmaxf(mx, __shfl_xor_sync(0xffffffffu, mx, o));
    }
    __shared__ float smn[8], smx[8];
    int w = threadIdx.x >> 5;
    if ((threadIdx.x & 31) == 0) { smn[w] = mn; smx[w] = mx; }
    __syncthreads();
    if (threadIdx.x == 0) {
        #pragma unroll
        for (int k = 1; k < 8; k++) { mn = fminf(mn, smn[k]); mx = fmaxf(mx, smx[k]); }
        atomicMin(&g_mm[0], encf(mn));
        atomicMax(&g_mm[1], encf(mx));
    }
}

// ----- bin value t in [0, 255.75];  bin = (int)t (<=255 by construction) ----
// fast path: t = min(fma(640, lg2(v + c1), -c2), 255.75)   [4 ops + MUFU]
//   where c1 = mx-2mn, c2 = 640*log2(mx-mn)  (log-quotient identity)
// precise path (guard fallback): original formula, same clamp -> same bins as
// min(int(min(640*log2f(1+(v-mn)*rcp),256)),255) since (int)255.75 == 255.
static __device__ __forceinline__ float tprec(float v, float mn, float rcp) {
    float m1 = fmaf(v - mn, rcp, 1.0f);
    return fminf(640.0f * log2f(m1), 255.75f);
}

// ---------------- pass B: bins + partial per-tile histograms ----------------
// 2048 CTAs x 256 threads: one quarter-tile (64 rows x 256 cols) per CTA.
// Guard: if any of the 4 t's is within 1.5e-3 of an integer boundary (fast
// path total error bound ~3.2e-4), recompute all 4 with the precise formula
// -> bin decisions identical to the precise version. Saturated t's are
// clamped to 255.75 (distance 0.25 from rint -> never trigger the guard).
// Bin 255 is never counted: hist[255] = 16384 - sum(other bins), computed in
// the merge epilogue. Non-255 pixels use fire-and-forget per-warp smem atomics.
__global__ void __launch_bounds__(256) k_hist(const float* __restrict__ x) {
    __shared__ unsigned hst[8 * NBINS];
    __shared__ unsigned shw[8];
    int t = threadIdx.x, wid = t >> 5, lane = t & 31;
    for (int i = t; i < 8 * NBINS; i += 256) hst[i] = 0;

    float mn  = decf(g_mm[0]);
    float mx  = decf(g_mm[1]);
    float rcp = 1.0f / (mx - mn);
    float c1  = mx - 2.0f * mn;
    float c2  = 640.0f * log2f(mx - mn);

    int sub  = blockIdx.x & 3;
    int tile = blockIdx.x >> 2;               // img*64 + ty*8 + tx
    int img = tile >> 6, ty = (tile >> 3) & 7, tx = tile & 7;
    int row0 = ty * 256 + sub * 64, col0 = tx * 256;
    int rl = t >> 6;                          // 0..3
    int c4 = t & 63;                          // 0..63 float4 per row
    __syncthreads();

    unsigned* myh = &hst[wid * NBINS];
    #pragma unroll 4
    for (int it = 0; it < 16; ++it) {
        int r = row0 + rl + it * 4;
        int g = (img * IMG_H + r) * IMG_W + col0 + c4 * 4;
        float4 v4 = __ldcs(reinterpret_cast<const float4*>(x + g));
        float t0 = fminf(fmaf(640.0f, __log2f(v4.x + c1), -c2), 255.75f);
        float t1 = fminf(fmaf(640.0f, __log2f(v4.y + c1), -c2), 255.75f);
        float t2 = fminf(fmaf(640.0f, __log2f(v4.z + c1), -c2), 255.75f);
        float t3 = fminf(fmaf(640.0f, __log2f(v4.w + c1), -c2), 255.75f);
        float d0 = fabsf(t0 - rintf(t0));
        float d1 = fabsf(t1 - rintf(t1));
        float d2 = fabsf(t2 - rintf(t2));
        float d3 = fabsf(t3 - rintf(t3));
        float dmin = fminf(fminf(d0, d1), fminf(d2, d3));
        if (dmin < 1.5e-3f) {                  // rare boundary case
            t0 = tprec(v4.x, mn, rcp);
            t1 = tprec(v4.y, mn, rcp);
            t2 = tprec(v4.z, mn, rcp);
            t3 = tprec(v4.w, mn, rcp);
        }
        int b0 = (int)t0;
        int b1 = (int)t1;
        int b2 = (int)t2;
        int b3 = (int)t3;
        *reinterpret_cast<uchar4*>(g_bins + g) =
            make_uchar4((unsigned char)b0, (unsigned char)b1,
                        (unsigned char)b2, (unsigned char)b3);
        if (t0 < 255.0f) atomicAdd(&myh[b0], 1u);
        if (t1 < 255.0f) atomicAdd(&myh[b1], 1u);
        if (t2 < 255.0f) atomicAdd(&myh[b2], 1u);
        if (t3 < 255.0f) atomicAdd(&myh[b3], 1u);
    }
    __syncthreads();

    unsigned h = 0;
    #pragma unroll
    for (int w2 = 0; w2 < 8; ++w2) h += hst[w2 * NBINS + t];
    // block-wide sum of non-255 counts -> bin 255 by subtraction
    unsigned s = h;
    #pragma unroll
    for (int o = 16; o; o >>= 1) s += __shfl_xor_sync(0xffffffffu, s, o);
    if (lane == 0) shw[wid] = s;
    __syncthreads();
    if (t == 255) {
        unsigned tot = 0;
        #pragma unroll
        for (int i = 0; i < 8; i++) tot += shw[i];
        h = 16384u - tot;                      // CTA covers exactly 16384 px
    }
    g_part[blockIdx.x * NBINS + t] = h;
}

// ---------------- pass C: merge partials, clip, redistribute, CDF -> LUT ----
__global__ void __launch_bounds__(256) k_lut() {
    __shared__ int sh_part[8];
    __shared__ int sh_wsum[8];
    __shared__ int sh_excess;
    int t = threadIdx.x, wid = t >> 5, lane = t & 31;
    int tile = blockIdx.x;

    int h = 0;
    #pragma unroll
    for (int s = 0; s < 4; ++s) h += (int)g_part[(tile * 4 + s) * NBINS + t];

    int e = h > CLIP_MAX ? h - CLIP_MAX : 0;
    h = h < CLIP_MAX ? h : CLIP_MAX;
    int er = e;
    #pragma unroll
    for (int o = 16; o; o >>= 1) er += __shfl_xor_sync(0xffffffffu, er, o);
    if (lane == 0) sh_part[wid] = er;
    __syncthreads();
    if (t == 0) {
        int ex = 0;
        #pragma unroll
        for (int i = 0; i < 8; i++) ex += sh_part[i];
        sh_excess = ex;
    }
    __syncthreads();
    int ex = sh_excess;
    int v = h + (ex >> 8) + (t < (ex & 255) ? 1 : 0);
    #pragma unroll
    for (int o = 1; o < 32; o <<= 1) {
        int n = __shfl_up_sync(0xffffffffu, v, o);
        if (lane >= o) v += n;
    }
    if (lane == 31) sh_wsum[wid] = v;
    __syncthreads();
    int pre = 0;
    for (int w2 = 0; w2 < wid; ++w2) pre += sh_wsum[w2];
    float cs = (float)(v + pre);                      // exact (< 2^24)
    float lv = fminf(fmaxf(floorf(cs * (255.0f / 65536.0f)), 0.0f), 255.0f);
    g_lut8[tile * NBINS + t] = (unsigned char)(int)lv;
}

// biased byte -> float: PRMT builds (2^23 + b); differences of biased values
// are exact, so only the lerp base needs the -2^23 debias.
static __device__ __forceinline__ float b2fb(unsigned p, int sel) {
    return __uint_as_float(__byte_perm(p, 0x4B000000u, sel));
}

// ---------------- passes D/E: packed-LUT bilinear interp --------------------
// CTA covers 64 rows x 128 cols (never straddles a tile-cell boundary), so
// the 4 neighbor LUTs are fixed. They are packed 4x u8 into one u32 per bin
// -> one LDS.32 per pixel (mostly broadcast given the bin-255 skew).
template <bool WRITE>
__global__ void __launch_bounds__(256) k_interp(float* __restrict__ out) {
    __shared__ unsigned sPu[NBINS];     // packed (L00,L01,L10,L11)
    __shared__ float smn[8];

    int t = threadIdx.x;
    int img   = blockIdx.z;
    int xBase = blockIdx.x * 128;
    int yBase = blockIdx.y * 64;

    float tyf = floorf((yBase + 0.5f) * (1.0f / 256.0f) - 0.5f);
    int y0 = min(max((int)tyf,     0), 7);
    int y1 = min(max((int)tyf + 1, 0), 7);
    float txf = floorf((xBase + 0.5f) * (1.0f / 256.0f) - 0.5f);
    int x0 = min(max((int)txf,     0), 7);
    int x1 = min(max((int)txf + 1, 0), 7);

    const unsigned char* lutB = g_lut8 + img * (64 * NBINS);
    {
        unsigned L00 = lutB[(y0 * 8 + x0) * NBINS + t];
        unsigned L01 = lutB[(y0 * 8 + x1) * NBINS + t];
        unsigned L10 = lutB[(y1 * 8 + x0) * NBINS + t];
        unsigned L11 = lutB[(y1 * 8 + x1) * NBINS + t];
        sPu[t] = L00 | (L01 << 8) | (L10 << 16) | (L11 << 24);
    }
    __syncthreads();

    float sN = 0.0f, oN = 0.0f;
    if (WRITE) {
        float a = decf(g_mm[2]) * (1.0f / 255.0f);
        float b = decf(g_mm[3]) * (1.0f / 255.0f);   // == 1.0
        float rinv = 1.0f / (b - a);
        sN = rinv * (1.0f / 255.0f);    // res = v*sN + oN
        oN = -a * rinv;
    }

    int r0 = t >> 5;     // 0..7
    int c4 = t & 31;     // 0..31 (uchar4 per row)

    // per-column wx (constant across rows for this thread)
    float wxs[4];
    #pragma unroll
    for (int j = 0; j < 4; j++) {
        float txx = (xBase + c4 * 4 + j + 0.5f) * (1.0f / 256.0f) - 0.5f;
        wxs[j] = txx - floorf(txx);
    }

    float vmn = 3.402823466e38f;

    #pragma unroll
    for (int it = 0; it < 8; ++it) {
        int y = yBase + r0 + it * 8;
        float tyy = (y + 0.5f) * (1.0f / 256.0f) - 0.5f;
        float wy = tyy - floorf(tyy);
        int g = (img * IMG_H + y) * IMG_W + xBase + c4 * 4;
        uchar4 pb = *reinterpret_cast<const uchar4*>(g_bins + g);
        float res[4];
        #pragma unroll
        for (int j = 0; j < 4; j++) {
            int b = (j == 0) ? pb.x : (j == 1) ? pb.y : (j == 2) ? pb.z : pb.w;
            unsigned p = sPu[b];
            float F00 = b2fb(p, 0x7440);              // 2^23 + f00
            float F01 = b2fb(p, 0x7441);
            float F10 = b2fb(p, 0x7442);
            float F11 = b2fb(p, 0x7443);
            float f00 = F00 - 8388608.0f;
            float f10 = F10 - 8388608.0f;
            float top = fmaf(wxs[j], F01 - F00, f00); // F01-F00 == f01-f00 exact
            float bot = fmaf(wxs[j], F11 - F10, f10);
            float v   = fmaf(wy, bot - top, top);
            if (WRITE) {
                res[j] = fmaf(v, sN, oN);
            } else {
                vmn = fminf(vmn, v);
            }
        }
        if (WRITE)
            __stcs(reinterpret_cast<float4*>(out + g),
                   make_float4(res[0], res[1], res[2], res[3]));
    }

    if (!WRITE) {
        #pragma unroll
        for (int o = 16; o; o >>= 1)
            vmn = fminf(vmn, __shfl_xor_sync(0xffffffffu, vmn, o));
        if ((t & 31) == 0) smn[t >> 5] = vmn;
        __syncthreads();
        if (t == 0) {
            #pragma unroll
            for (int i = 1; i < 8; i++) vmn = fminf(vmn, smn[i]);
            atomicMin(&g_mm[2], encf(vmn));
        }
    }
}

// ---------------- launch ----------------------------------------------------
// Order chosen so k_hist is the 4th launch (the one ncu captures).
extern "C" void kernel_launch(void* const* d_in, const int* in_sizes, int n_in,
                              void* d_out, int out_size) {
    const float* x = (const float*)d_in[0];
    float* out = (float*)d_out;

    k_init_a<<<1, 32>>>();                                   // 1
    k_minmax_in<<<1024, 256>>>((const float4*)x, NPIX / 4);  // 2
    k_init_b<<<1, 32>>>();                                   // 3
    k_hist<<<NSUB, 256>>>(x);                                // 4  <- profiled slot
    k_lut<<<NTILES, 256>>>();                                // 5
    dim3 gi(IMG_W / 128, IMG_H / 64, NIMG);
    k_interp<false><<<gi, 256>>>(out);                       // 6
    k_interp<true><<<gi, 256>>>(out);                        // 7
}

// round 10
// speedup vs baseline: 1.7261x; 1.0141x over previous
#include <cuda_runtime.h>
#include <math_constants.h>

#define IMG_H 2048
#define IMG_W 2048
#define NIMG 8
#define NBINS 256
#define NTILES 512                 // 8 images * 8*8 grid
#define NPIX (NIMG*IMG_H*IMG_W)
#define CLIP_MAX 256               // max(int(1.0*65536//256),1)
#define NSUB 2048                  // 4 sub-blocks per tile
#define MM_GRID 1024               // minmax grid

// ---------------- device scratch (statics; no allocations allowed) ----------
__device__ unsigned char g_bins[NPIX];              // 33.5 MB per-pixel bin
__device__ unsigned char g_lut8[NTILES * NBINS];    // per-tile LUT (ints 0..255)
__device__ unsigned int  g_part[NSUB * NBINS];      // partial histograms
// enc(min_x), enc(max_x), enc(min_v), enc(max_v)=enc(255.0f)=0xC37F0000
__device__ unsigned int  g_mm[4] = {0xFFFFFFFFu, 0u, 0xFFFFFFFFu, 0xC37F0000u};
__device__ unsigned int  g_ctr = 0;                 // last-CTA counter (self-reset)
__device__ float         g_bounds[NBINS];           // exact bin lower boundaries
__device__ float         g_cb[2];                   // c1 = mx-2mn, c2 = 640*log2(mx-mn)

static __device__ __forceinline__ unsigned encf(float f) {
    unsigned u = __float_as_uint(f);
    return (u & 0x80000000u) ? ~u : (u | 0x80000000u);
}
static __device__ __forceinline__ float decf(unsigned u) {
    return (u & 0x80000000u) ? __uint_as_float(u ^ 0x80000000u)
                             : __uint_as_float(~u);
}

// precise reference bin value (truth the fast path reproduces exactly)
static __device__ __forceinline__ int binprec(float v, float mn, float rcp) {
    float m1 = fmaf(v - mn, rcp, 1.0f);
    return (int)fminf(640.0f * log2f(m1), 255.75f);
}

// ---------------- pass 1: global min/max + (last CTA) exact boundary table --
__global__ void __launch_bounds__(256) k_minmax_in(const float4* __restrict__ x, int n4) {
    float mn = 3.402823466e38f, mx = -3.402823466e38f;
    int stride = gridDim.x * blockDim.x;
    int i = blockIdx.x * blockDim.x + threadIdx.x;
    for (; i + 3 * stride < n4; i += 4 * stride) {
        float4 a = __ldcs(x + i);
        float4 b = __ldcs(x + i + stride);
        float4 c = __ldcs(x + i + 2 * stride);
        float4 d = __ldcs(x + i + 3 * stride);
        mn = fminf(mn, fminf(fminf(a.x, a.y), fminf(a.z, a.w)));
        mx = fmaxf(mx, fmaxf(fmaxf(a.x, a.y), fmaxf(a.z, a.w)));
        mn = fminf(mn, fminf(fminf(b.x, b.y), fminf(b.z, b.w)));
        mx = fmaxf(mx, fmaxf(fmaxf(b.x, b.y), fmaxf(b.z, b.w)));
        mn = fminf(mn, fminf(fminf(c.x, c.y), fminf(c.z, c.w)));
        mx = fmaxf(mx, fmaxf(fmaxf(c.x, c.y), fmaxf(c.z, c.w)));
        mn = fminf(mn, fminf(fminf(d.x, d.y), fminf(d.z, d.w)));
        mx = fmaxf(mx, fmaxf(fmaxf(d.x, d.y), fmaxf(d.z, d.w)));
    }
    for (; i < n4; i += stride) {
        float4 a = __ldcs(x + i);
        mn = fminf(mn, fminf(fminf(a.x, a.y), fminf(a.z, a.w)));
        mx = fmaxf(mx, fmaxf(fmaxf(a.x, a.y), fmaxf(a.z, a.w)));
    }
    #pragma unroll
    for (int o = 16; o; o >>= 1) {
        mn = fminf(mn, __shfl_xor_sync(0xffffffffu, mn, o));
        mx = fmaxf(mx, __shfl_xor_sync(0xffffffffu, mx, o));
    }
    __shared__ float smn[8], smx[8];
    __shared__ int isLast;
    int w = threadIdx.x >> 5;
    if ((threadIdx.x & 31) == 0) { smn[w] = mn; smx[w] = mx; }
    __syncthreads();
    if (threadIdx.x == 0) {
        #pragma unroll
        for (int k = 1; k < 8; k++) { mn = fminf(mn, smn[k]); mx = fmaxf(mx, smx[k]); }
        atomicMin(&g_mm[0], encf(mn));
        atomicMax(&g_mm[1], encf(mx));
        __threadfence();
        isLast = (atomicAdd(&g_ctr, 1u) == MM_GRID - 1);
    }
    __syncthreads();

    if (isLast) {
        __threadfence();                      // acquire all CTAs' g_mm updates
        float gmn = decf(*(volatile unsigned*)&g_mm[0]);
        float gmx = decf(*(volatile unsigned*)&g_mm[1]);
        float rcp = 1.0f / (gmx - gmn);
        int t = threadIdx.x;
        if (t == 0) {
            g_cb[0] = gmx - 2.0f * gmn;
            g_cb[1] = 640.0f * log2f(gmx - gmn);
            g_bounds[0] = -CUDART_INF_F;      // bin 0: never decrement below
            g_mm[2] = 0xFFFFFFFFu;            // reset min_v accumulator
            g_ctr = 0;                        // self-reset for next replay
        } else {
            // bisect (in positive-float bit space) the smallest v in [gmn,gmx]
            // with binprec(v) >= t.  binprec(gmn)=0<t, binprec(gmx)=255>=t.
            unsigned lo = __float_as_uint(gmn), hi = __float_as_uint(gmx);
            while (lo + 1u < hi) {
                unsigned mid = (lo + hi) >> 1;
                if (binprec(__uint_as_float(mid), gmn, rcp) >= t) hi = mid;
                else lo = mid;
            }
            g_bounds[t] = __uint_as_float(hi);
        }
    }
}

// ---------------- pass 2: bins + partial per-tile histograms ----------------
// 2048 CTAs x 256 threads, one quarter-tile (64 x 256) each.
// Fast path: t = fma(640, MUFU.LG2(v + c1), delta - c2), delta = 1.5e-3 bin
// units (> total fast-path error bound ~5.7e-4), so floor(t) is b_true or
// b_true+1. One exact down-fixup against the bisected boundary table makes
// bins bit-identical to the precise formula. No branches, no slow path.
// Bin 255 (~68%) never touches the histogram: recovered by subtraction.
__global__ void __launch_bounds__(256) k_hist(const float* __restrict__ x) {
    __shared__ unsigned hst[8 * NBINS];
    __shared__ float sb[NBINS];
    __shared__ unsigned shw[8];
    int t = threadIdx.x, wid = t >> 5, lane = t & 31;
    for (int i = t; i < 8 * NBINS; i += 256) hst[i] = 0;
    sb[t] = g_bounds[t];

    float c1  = g_cb[0];
    float c2b = 1.5e-3f - g_cb[1];            // upward bias folded in

    int sub  = blockIdx.x & 3;
    int tile = blockIdx.x >> 2;               // img*64 + ty*8 + tx
    int img = tile >> 6, ty = (tile >> 3) & 7, tx = tile & 7;
    int row0 = ty * 256 + sub * 64, col0 = tx * 256;
    int rl = t >> 6;                          // 0..3
    int c4 = t & 63;                          // 0..63 float4 per row
    __syncthreads();

    unsigned* myh = &hst[wid * NBINS];
    #pragma unroll 4
    for (int it = 0; it < 16; ++it) {
        int r = row0 + rl + it * 4;
        int g = (img * IMG_H + r) * IMG_W + col0 + c4 * 4;
        float4 v4 = __ldcs(reinterpret_cast<const float4*>(x + g));
        float t0 = fmaf(640.0f, __log2f(v4.x + c1), c2b);
        float t1 = fmaf(640.0f, __log2f(v4.y + c1), c2b);
        float t2 = fmaf(640.0f, __log2f(v4.z + c1), c2b);
        float t3 = fmaf(640.0f, __log2f(v4.w + c1), c2b);
        int b0 = min(__float2int_rd(t0), 255);
        int b1 = min(__float2int_rd(t1), 255);
        int b2 = min(__float2int_rd(t2), 255);
        int b3 = min(__float2int_rd(t3), 255);
        b0 -= (v4.x < sb[b0]);                // exact fixup (at most -1)
        b1 -= (v4.y < sb[b1]);
        b2 -= (v4.z < sb[b2]);
        b3 -= (v4.w < sb[b3]);
        *reinterpret_cast<uchar4*>(g_bins + g) =
            make_uchar4((unsigned char)b0, (unsigned char)b1,
                        (unsigned char)b2, (unsigned char)b3);
        if (b0 < 255) atomicAdd(&myh[b0], 1u);
        if (b1 < 255) atomicAdd(&myh[b1], 1u);
        if (b2 < 255) atomicAdd(&myh[b2], 1u);
        if (b3 < 255) atomicAdd(&myh[b3], 1u);
    }
    __syncthreads();

    unsigned h = 0;
    #pragma unroll
    for (int w2 = 0; w2 < 8; ++w2) h += hst[w2 * NBINS + t];
    // block-wide sum of non-255 counts -> bin 255 by subtraction
    unsigned s = h;
    #pragma unroll
    for (int o = 16; o; o >>= 1) s += __shfl_xor_sync(0xffffffffu, s, o);
    if (lane == 0) shw[wid] = s;
    __syncthreads();
    if (t == 255) {
        unsigned tot = 0;
        #pragma unroll
        for (int i = 0; i < 8; i++) tot += shw[i];
        h = 16384u - tot;                      // CTA covers exactly 16384 px
    }
    g_part[blockIdx.x * NBINS + t] = h;
}

// ---------------- pass 3: merge partials, clip, redistribute, CDF -> LUT ----
__global__ void __launch_bounds__(256) k_lut() {
    __shared__ int sh_part[8];
    __shared__ int sh_wsum[8];
    __shared__ int sh_excess;
    int t = threadIdx.x, wid = t >> 5, lane = t & 31;
    int tile = blockIdx.x;

    // reset input-min/max accumulators for the next replay (consumed already)
    if (tile == 0 && t == 0) { g_mm[0] = 0xFFFFFFFFu; g_mm[1] = 0u; }

    int h = 0;
    #pragma unroll
    for (int s = 0; s < 4; ++s) h += (int)g_part[(tile * 4 + s) * NBINS + t];

    int e = h > CLIP_MAX ? h - CLIP_MAX : 0;
    h = h < CLIP_MAX ? h : CLIP_MAX;
    int er = e;
    #pragma unroll
    for (int o = 16; o; o >>= 1) er += __shfl_xor_sync(0xffffffffu, er, o);
    if (lane == 0) sh_part[wid] = er;
    __syncthreads();
    if (t == 0) {
        int ex = 0;
        #pragma unroll
        for (int i = 0; i < 8; i++) ex += sh_part[i];
        sh_excess = ex;
    }
    __syncthreads();
    int ex = sh_excess;
    int v = h + (ex >> 8) + (t < (ex & 255) ? 1 : 0);
    #pragma unroll
    for (int o = 1; o < 32; o <<= 1) {
        int n = __shfl_up_sync(0xffffffffu, v, o);
        if (lane >= o) v += n;
    }
    if (lane == 31) sh_wsum[wid] = v;
    __syncthreads();
    int pre = 0;
    for (int w2 = 0; w2 < wid; ++w2) pre += sh_wsum[w2];
    float cs = (float)(v + pre);                      // exact (< 2^24)
    float lv = fminf(fmaxf(floorf(cs * (255.0f / 65536.0f)), 0.0f), 255.0f);
    g_lut8[tile * NBINS + t] = (unsigned char)(int)lv;
}

// biased byte -> float: PRMT builds (2^23 + b); differences of biased values
// are exact, so only the lerp base needs the -2^23 debias.
static __device__ __forceinline__ float b2fb(unsigned p, int sel) {
    return __uint_as_float(__byte_perm(p, 0x4B000000u, sel));
}

// ---------------- passes 4/5: packed-LUT bilinear interp --------------------
// CTA covers 64 rows x 128 cols (never straddles a tile-cell boundary), so
// the 4 neighbor LUTs are fixed; packed 4x u8 into one u32 per bin -> one
// LDS.32 per pixel (mostly broadcast given the bin-255 skew).
template <bool WRITE>
__global__ void __launch_bounds__(256) k_interp(float* __restrict__ out) {
    __shared__ unsigned sPu[NBINS];     // packed (L00,L01,L10,L11)
    __shared__ float smn[8];

    int t = threadIdx.x;
    int img   = blockIdx.z;
    int xBase = blockIdx.x * 128;
    int yBase = blockIdx.y * 64;

    float tyf = floorf((yBase + 0.5f) * (1.0f / 256.0f) - 0.5f);
    int y0 = min(max((int)tyf,     0), 7);
    int y1 = min(max((int)tyf + 1, 0), 7);
    float txf = floorf((xBase + 0.5f) * (1.0f / 256.0f) - 0.5f);
    int x0 = min(max((int)txf,     0), 7);
    int x1 = min(max((int)txf + 1, 0), 7);

    const unsigned char* lutB = g_lut8 + img * (64 * NBINS);
    {
        unsigned L00 = lutB[(y0 * 8 + x0) * NBINS + t];
        unsigned L01 = lutB[(y0 * 8 + x1) * NBINS + t];
        unsigned L10 = lutB[(y1 * 8 + x0) * NBINS + t];
        unsigned L11 = lutB[(y1 * 8 + x1) * NBINS + t];
        sPu[t] = L00 | (L01 << 8) | (L10 << 16) | (L11 << 24);
    }
    __syncthreads();

    float sN = 0.0f, oN = 0.0f;
    if (WRITE) {
        float a = decf(g_mm[2]) * (1.0f / 255.0f);
        float b = decf(g_mm[3]) * (1.0f / 255.0f);   // == 1.0
        float rinv = 1.0f / (b - a);
        sN = rinv * (1.0f / 255.0f);    // res = v*sN + oN
        oN = -a * rinv;
    }

    int r0 = t >> 5;     // 0..7
    int c4 = t & 31;     // 0..31 (uchar4 per row)

    float wxs[4];
    #pragma unroll
    for (int j = 0; j < 4; j++) {
        float txx = (xBase + c4 * 4 + j + 0.5f) * (1.0f / 256.0f) - 0.5f;
        wxs[j] = txx - floorf(txx);
    }

    float vmn = 3.402823466e38f;

    #pragma unroll
    for (int it = 0; it < 8; ++it) {
        int y = yBase + r0 + it * 8;
        float tyy = (y + 0.5f) * (1.0f / 256.0f) - 0.5f;
        float wy = tyy - floorf(tyy);
        int g = (img * IMG_H + y) * IMG_W + xBase + c4 * 4;
        uchar4 pb = *reinterpret_cast<const uchar4*>(g_bins + g);
        float res[4];
        #pragma unroll
        for (int j = 0; j < 4; j++) {
            int b = (j == 0) ? pb.x : (j == 1) ? pb.y : (j == 2) ? pb.z : pb.w;
            unsigned p = sPu[b];
            float F00 = b2fb(p, 0x7440);              // 2^23 + f00
            float F01 = b2fb(p, 0x7441);
            float F10 = b2fb(p, 0x7442);
            float F11 = b2fb(p, 0x7443);
            float f00 = F00 - 8388608.0f;
            float f10 = F10 - 8388608.0f;
            float top = fmaf(wxs[j], F01 - F00, f00); // F01-F00 == f01-f00 exact
            float bot = fmaf(wxs[j], F11 - F10, f10);
            float v   = fmaf(wy, bot - top, top);
            if (WRITE) {
                res[j] = fmaf(v, sN, oN);
            } else {
                vmn = fminf(vmn, v);
            }
        }
        if (WRITE)
            __stcs(reinterpret_cast<float4*>(out + g),
                   make_float4(res[0], res[1], res[2], res[3]));
    }

    if (!WRITE) {
        #pragma unroll
        for (int o = 16; o; o >>= 1)
            vmn = fminf(vmn, __shfl_xor_sync(0xffffffffu, vmn, o));
        if ((t & 31) == 0) smn[t >> 5] = vmn;
        __syncthreads();
        if (t == 0) {
            #pragma unroll
            for (int i = 1; i < 8; i++) vmn = fminf(vmn, smn[i]);
            atomicMin(&g_mm[2], encf(vmn));
        }
    }
}

// ---------------- launch ----------------------------------------------------
// 5 launches; k_interp<0> sits in slot 4 (the slot ncu captures).
extern "C" void kernel_launch(void* const* d_in, const int* in_sizes, int n_in,
                              void* d_out, int out_size) {
    const float* x = (const float*)d_in[0];
    float* out = (float*)d_out;

    k_minmax_in<<<MM_GRID, 256>>>((const float4*)x, NPIX / 4);  // 1 (+bounds tail)
    k_hist<<<NSUB, 256>>>(x);                                   // 2
    k_lut<<<NTILES, 256>>>();                                   // 3 (+resets)
    dim3 gi(IMG_W / 128, IMG_H / 64, NIMG);
    k_interp<false><<<gi, 256>>>(out);                          // 4  <- profiled slot
    k_interp<true><<<gi, 256>>>(out);                           // 5
}